// round 8
// baseline (speedup 1.0000x reference)
#include <cuda_runtime.h>
#include <cuda_fp16.h>

#define B_   32
#define T_   4096
#define D_   256
#define DQ_  512
#define E_   256

// ---------------- scratch (static device globals) ----------------
__device__ float g_scores[B_ * T_];
__device__ float g_projq[B_ * E_];
__device__ float g_sum[B_];
__device__ float g_inv[B_];
__device__ __align__(16) __half g_Wvf[E_ * D_];   // [e][k] transposed fp16

// ---------------- helpers ----------------
__device__ __forceinline__ unsigned smem_u32(const void* p) {
    unsigned a;
    asm("{ .reg .u64 t; cvta.to.shared.u64 t, %1; cvt.u32.u64 %0, t; }"
        : "=r"(a) : "l"(p));
    return a;
}
__device__ __forceinline__ unsigned sw128(unsigned b) { return b ^ ((b >> 3) & 0x70); }

__device__ __forceinline__ void ldsm4(unsigned r[4], unsigned addr) {
    asm volatile("ldmatrix.sync.aligned.m8n8.x4.shared.b16 {%0,%1,%2,%3}, [%4];"
                 : "=r"(r[0]), "=r"(r[1]), "=r"(r[2]), "=r"(r[3]) : "r"(addr));
}
__device__ __forceinline__ void mma16816(float d[4], const unsigned a[4],
                                         unsigned b0, unsigned b1) {
    asm volatile(
        "mma.sync.aligned.m16n8k16.row.col.f32.f16.f16.f32 "
        "{%0,%1,%2,%3}, {%4,%5,%6,%7}, {%8,%9}, {%0,%1,%2,%3};"
        : "+f"(d[0]), "+f"(d[1]), "+f"(d[2]), "+f"(d[3])
        : "r"(a[0]), "r"(a[1]), "r"(a[2]), "r"(a[3]), "r"(b0), "r"(b1));
}
__device__ __forceinline__ void cpasync16(unsigned dst, const void* src) {
    asm volatile("cp.async.cg.shared.global [%0], [%1], 16;" :: "r"(dst), "l"(src));
}
__device__ __forceinline__ void cp_commit() { asm volatile("cp.async.commit_group;"); }
__device__ __forceinline__ void cp_wait0()  { asm volatile("cp.async.wait_group 0;" ::: "memory"); }

// fast tanh: 1 - 2/(e^{2x}+1); MUFU-based, saturates correctly
__device__ __forceinline__ float fast_tanh(float x) {
    float e = __expf(2.f * x);
    return 1.f - __fdividef(2.f, e + 1.f);
}

// smem layout (bytes): stage = A fp16 (8KB) + B fp16 (32KB) = 40KB
#define STG_        40960
#define SB_A(s)     ((s) * STG_)
#define SB_B(s)     ((s) * STG_ + 8192)
#define SB_PQ       (2 * STG_)
#define SB_W        (2 * STG_ + 1024)
#define SB_RED      (2 * STG_ + 2048)
#define SMEM_TOTAL  (2 * STG_ + 2048 + 64 * 5 * 4)

// ---------------- prep: Wv->fp16T, proj_q, zero out-attn & g_sum ----------------
__global__ void prep_kernel(const float* __restrict__ Wv,
                            const float* __restrict__ query,
                            const float* __restrict__ Wu,
                            float* __restrict__ out) {
    const int blk = blockIdx.x;
    const int tid = threadIdx.x;   // 256
    if (blk < 256) {
        // Wv split: k = blk, e = tid
        g_Wvf[tid * D_ + blk] = __float2half(Wv[blk * E_ + tid]);
        if (blk < 32) out[blk * 256 + tid] = 0.f;   // zero attn region (B*D = 8192)
    } else {
        // proj_q for b = blk - 256
        const int b = blk - 256;
        __shared__ float q[DQ_];
        q[tid]       = query[b * DQ_ + tid];
        q[tid + 256] = query[b * DQ_ + tid + 256];
        __syncthreads();
        float acc = 0.f;
#pragma unroll 8
        for (int k = 0; k < DQ_; k++)
            acc = fmaf(q[k], Wu[k * E_ + tid], acc);
        g_projq[b * E_ + tid] = acc;
        if (tid == 0) g_sum[b] = 0.f;
    }
}

// ---------------- fused mma.sync fp16 GEMM + tanh + score + exp-sum ----------------
// 256 threads / 8 warps as 2 m-groups x 4 n-groups; 2 CTAs/SM.
// Tile M=64 tok x N=256 e x K=256. Warp (wm, wn): tokens [32wm,32wm+32),
// e-slice [64wn, 64wn+64).
__global__ void __launch_bounds__(256, 2) score_kernel(
    const float* __restrict__ values,
    const float* __restrict__ Wscore) {

    extern __shared__ char sm[];
    const unsigned sb = smem_u32(sm);
    const int tid = threadIdx.x, wid = tid >> 5, lane = tid & 31;
    const int wm = wid >> 2, wn = wid & 3;
    const int b = blockIdx.y, t0 = blockIdx.x * 64;

    // pq / Wscore into smem
    {
        ((float*)(sm + SB_PQ))[tid] = g_projq[b * E_ + tid];
        ((float*)(sm + SB_W))[tid]  = Wscore[tid];
    }

    // loader index split
    const int tx = tid & 15, ry = tid >> 4;   // A: 16 float4-cols x 16 rows
    const int u  = tid & 7,  eb = tid >> 3;   // B: 8 16B-units x 32 e-rows
    const float4* vsrc = (const float4*)(values + ((size_t)b * T_ + t0) * D_);

    // per-lane ldmatrix geometry
    const unsigned arow  = lane & 15;
    const unsigned akoff = (lane >> 4) << 4;          // 0 or 16 bytes
    const unsigned brow  = (lane & 7) + ((lane & 16) >> 1);
    const unsigned bkoff = (lane & 8) << 1;           // 0 or 16 bytes

    float acc[2][8][4];
#pragma unroll
    for (int m = 0; m < 2; m++)
#pragma unroll
        for (int n = 0; n < 8; n++)
#pragma unroll
            for (int i = 0; i < 4; i++) acc[m][n][i] = 0.f;

    // ---- A chunk loader pieces (64 rows x 64 k-floats per chunk) ----
    float4 pv[4];
    auto lda = [&](int c) {
#pragma unroll
        for (int p = 0; p < 4; p++)
            pv[p] = vsrc[(size_t)(ry + 16 * p) * 64 + c * 16 + tx];
    };
    auto sta = [&](int s) {
        char* a = sm + SB_A(s);
#pragma unroll
        for (int p = 0; p < 4; p++) {
            const int row = ry + 16 * p;
            float4 v = pv[p];
            unsigned h01, h23;
            asm("cvt.rn.f16x2.f32 %0, %1, %2;" : "=r"(h01) : "f"(v.y), "f"(v.x));
            asm("cvt.rn.f16x2.f32 %0, %1, %2;" : "=r"(h23) : "f"(v.w), "f"(v.z));
            unsigned off = sw128((unsigned)(row * 128 + tx * 8));
            *(uint2*)(a + off) = make_uint2(h01, h23);
        }
    };
    auto ldb = [&](int c, int s) {
#pragma unroll
        for (int p = 0; p < 8; p++) {
            const int e = eb + 32 * p;
            const unsigned doff = sw128((unsigned)(e * 128 + u * 16));
            cpasync16(sb + SB_B(s) + doff, g_Wvf + (size_t)e * D_ + c * 64 + u * 8);
        }
        cp_commit();
    };

    // prologue: chunk 0 -> stage 0
    lda(0);
    ldb(0, 0);
    sta(0);
    cp_wait0();
    __syncthreads();

    for (int c = 0; c < 4; c++) {
        const int s = c & 1;
        if (c < 3) {                 // prefetch next chunk into other stage
            lda(c + 1);
            ldb(c + 1, s ^ 1);
        }
        // ---- compute chunk c from stage s ----
        const unsigned ab = sb + SB_A(s), bb = sb + SB_B(s);
#pragma unroll
        for (int kk = 0; kk < 4; kk++) {
            unsigned A[2][4];
#pragma unroll
            for (int mb = 0; mb < 2; mb++) {
                const unsigned aoff =
                    sw128((wm * 32 + mb * 16 + arow) * 128 + (unsigned)kk * 32 + akoff);
                ldsm4(A[mb], ab + aoff);
            }
#pragma unroll
            for (int g = 0; g < 4; g++) {
                unsigned Bv[4];
                const unsigned boff =
                    sw128((wn * 64 + g * 16 + brow) * 128 + (unsigned)kk * 32 + bkoff);
                ldsm4(Bv, bb + boff);
#pragma unroll
                for (int mb = 0; mb < 2; mb++) {
                    mma16816(acc[mb][2 * g],     A[mb], Bv[0], Bv[1]);
                    mma16816(acc[mb][2 * g + 1], A[mb], Bv[2], Bv[3]);
                }
            }
        }
        if (c < 3) {
            sta(s ^ 1);
            cp_wait0();
        }
        __syncthreads();
    }

    // ---- epilogue: tanh + dot(Wscore) + reduce + exp-sum atomic ----
    const float* pq = (const float*)(sm + SB_PQ);
    const float* w  = (const float*)(sm + SB_W);
    float* red = (float*)(sm + SB_RED);

    const int c0 = wn * 64 + (lane & 3) * 2;
#pragma unroll
    for (int mb = 0; mb < 2; mb++) {
        float r0 = 0.f, r1 = 0.f;
#pragma unroll
        for (int nb = 0; nb < 8; nb++) {
            const int ca = c0 + nb * 8, cb = ca + 1;
            const float pqa = pq[ca], pqb = pq[cb];
            const float wa = w[ca],  wb = w[cb];
            r0 += fast_tanh(acc[mb][nb][0] + pqa) * wa;
            r0 += fast_tanh(acc[mb][nb][1] + pqb) * wb;
            r1 += fast_tanh(acc[mb][nb][2] + pqa) * wa;
            r1 += fast_tanh(acc[mb][nb][3] + pqb) * wb;
        }
#pragma unroll
        for (int off = 1; off <= 2; off <<= 1) {
            r0 += __shfl_xor_sync(0xffffffffu, r0, off);
            r1 += __shfl_xor_sync(0xffffffffu, r1, off);
        }
        if ((lane & 3) == 0) {
            const int tok = wm * 32 + mb * 16 + (lane >> 2);
            red[tok * 5 + wn]       = r0;
            red[(tok + 8) * 5 + wn] = r1;
        }
    }
    __syncthreads();
    if (tid < 64) {
        float s = red[tid * 5] + red[tid * 5 + 1] + red[tid * 5 + 2] + red[tid * 5 + 3];
        g_scores[b * T_ + t0 + tid] = s;
        // fused exp-sum (no max shift: |score| <= ||Wscore||_1 ~ 13, no overflow)
        float e = __expf(s);
#pragma unroll
        for (int off = 16; off > 0; off >>= 1)
            e += __shfl_xor_sync(0xffffffffu, e, off);
        if (lane == 0) atomicAdd(&g_sum[b], e);
    }
}

// ---------------- inv: g_inv[b] = 1/g_sum[b] ----------------
__global__ void inv_kernel() {
    g_inv[threadIdx.x] = 1.f / g_sum[threadIdx.x];
}

// ---------------- fused: alignments + attentions (512-token tiles) ----------------
__global__ void attn_kernel(const float* __restrict__ values,
                            float* __restrict__ out) {
    const int b = blockIdx.y, t0 = blockIdx.x * 512, tid = threadIdx.x;  // 512 thr
    const int dg = tid & 63, tr = tid >> 6;  // 64 float4 d-groups x 8 token rails

    __shared__ float al[512];
    const float e = __expf(g_scores[(size_t)b * T_ + t0 + tid]) * g_inv[b];
    out[B_ * D_ + (size_t)b * T_ + t0 + tid] = e;   // alignments
    al[tid] = e;
    __syncthreads();

    const float4* vb = (const float4*)(values + ((size_t)b * T_ + t0) * D_);
    float4 acc = make_float4(0.f, 0.f, 0.f, 0.f);
#pragma unroll 4
    for (int t = tr; t < 512; t += 8) {
        float4 v = vb[(size_t)t * 64 + dg];
        float a = al[t];
        acc.x = fmaf(a, v.x, acc.x);
        acc.y = fmaf(a, v.y, acc.y);
        acc.z = fmaf(a, v.z, acc.z);
        acc.w = fmaf(a, v.w, acc.w);
    }
    float* attn = out + b * D_ + dg * 4;
    atomicAdd(attn + 0, acc.x);
    atomicAdd(attn + 1, acc.y);
    atomicAdd(attn + 2, acc.z);
    atomicAdd(attn + 3, acc.w);
}

// ---------------- launch ----------------
extern "C" void kernel_launch(void* const* d_in, const int* in_sizes, int n_in,
                              void* d_out, int out_size) {
    const float* query  = (const float*)d_in[0];
    const float* values = (const float*)d_in[1];
    const float* Wv     = (const float*)d_in[2];
    const float* Wu     = (const float*)d_in[3];
    const float* Wscore = (const float*)d_in[4];
    float* out = (float*)d_out;

    cudaFuncSetAttribute(score_kernel,
                         cudaFuncAttributeMaxDynamicSharedMemorySize, SMEM_TOTAL);

    prep_kernel<<<288, 256>>>(Wv, query, Wu, out);
    score_kernel<<<dim3(T_ / 64, B_), 256, SMEM_TOTAL>>>(values, Wscore);
    inv_kernel<<<1, B_>>>();
    attn_kernel<<<dim3(T_ / 512, B_), 512>>>(values, out);
}

// round 9
// speedup vs baseline: 1.1020x; 1.1020x over previous
#include <cuda_runtime.h>
#include <cuda_fp16.h>

#define B_   32
#define T_   4096
#define D_   256
#define DQ_  512
#define E_   256

// ---------------- scratch (static device globals) ----------------
__device__ float g_scores[B_ * T_];
__device__ float g_projq[B_ * E_];
__device__ float g_sum[B_];
__device__ float g_attn[B_ * D_];                 // unnormalized attention accum
__device__ __align__(16) __half g_Wvf[E_ * D_];   // [e][k] transposed fp16

// ---------------- helpers ----------------
__device__ __forceinline__ unsigned smem_u32(const void* p) {
    unsigned a;
    asm("{ .reg .u64 t; cvta.to.shared.u64 t, %1; cvt.u32.u64 %0, t; }"
        : "=r"(a) : "l"(p));
    return a;
}
__device__ __forceinline__ unsigned sw128(unsigned b) { return b ^ ((b >> 3) & 0x70); }

__device__ __forceinline__ void ldsm4(unsigned r[4], unsigned addr) {
    asm volatile("ldmatrix.sync.aligned.m8n8.x4.shared.b16 {%0,%1,%2,%3}, [%4];"
                 : "=r"(r[0]), "=r"(r[1]), "=r"(r[2]), "=r"(r[3]) : "r"(addr));
}
__device__ __forceinline__ void mma16816(float d[4], const unsigned a[4],
                                         unsigned b0, unsigned b1) {
    asm volatile(
        "mma.sync.aligned.m16n8k16.row.col.f32.f16.f16.f32 "
        "{%0,%1,%2,%3}, {%4,%5,%6,%7}, {%8,%9}, {%0,%1,%2,%3};"
        : "+f"(d[0]), "+f"(d[1]), "+f"(d[2]), "+f"(d[3])
        : "r"(a[0]), "r"(a[1]), "r"(a[2]), "r"(a[3]), "r"(b0), "r"(b1));
}
__device__ __forceinline__ void cpasync16(unsigned dst, const void* src) {
    asm volatile("cp.async.cg.shared.global [%0], [%1], 16;" :: "r"(dst), "l"(src));
}
__device__ __forceinline__ void cp_commit() { asm volatile("cp.async.commit_group;"); }
__device__ __forceinline__ void cp_wait0()  { asm volatile("cp.async.wait_group 0;" ::: "memory"); }

// fast tanh: 1 - 2/(e^{2x}+1); MUFU-based, saturates correctly
__device__ __forceinline__ float fast_tanh(float x) {
    float e = __expf(2.f * x);
    return 1.f - __fdividef(2.f, e + 1.f);
}

// smem layout (bytes):
//   A: 4 stages (one per K-chunk, kept live for the attn epilogue), 8KB each
//   B: 2 stages (double-buffered), 32KB each
#define SB_A(c)     ((c) * 8192)
#define SB_B(s)     (32768 + (s) * 32768)
#define SB_PQ       98304
#define SB_W        99328
#define SB_RED      100352                 // 64*5*4 = 1280
#define SB_WB       101632                 // 64 floats: exp(score)
#define SB_SAT      101888                 // 256 floats: CTA attn partial
#define SMEM_TOTAL  102912

// ---------------- prep: Wv->fp16T, proj_q, zero g_sum/g_attn ----------------
__global__ void prep_kernel(const float* __restrict__ Wv,
                            const float* __restrict__ query,
                            const float* __restrict__ Wu) {
    const int blk = blockIdx.x;
    const int tid = threadIdx.x;   // 256
    if (blk < 256) {
        // Wv split: k = blk, e = tid
        g_Wvf[tid * D_ + blk] = __float2half(Wv[blk * E_ + tid]);
    } else {
        // proj_q for b = blk - 256
        const int b = blk - 256;
        __shared__ float q[DQ_];
        q[tid]       = query[b * DQ_ + tid];
        q[tid + 256] = query[b * DQ_ + tid + 256];
        __syncthreads();
        float acc = 0.f;
#pragma unroll 8
        for (int k = 0; k < DQ_; k++)
            acc = fmaf(q[k], Wu[k * E_ + tid], acc);
        g_projq[b * E_ + tid] = acc;
        g_attn[b * D_ + tid] = 0.f;
        if (tid == 0) g_sum[b] = 0.f;
    }
}

// ---------------- fused: fp16 GEMM + tanh + score + exp-sum + attn partial ----
// 256 threads / 8 warps as 2 m-groups x 4 n-groups; 2 CTAs/SM.
// Tile M=64 tok x N=256 e x K=256. Warp (wm, wn): tokens [32wm,32wm+32),
// e-slice [64wn, 64wn+64). A tiles stay resident (4 stages) for the epilogue.
__global__ void __launch_bounds__(256, 2) score_kernel(
    const float* __restrict__ values,
    const float* __restrict__ Wscore) {

    extern __shared__ char sm[];
    const unsigned sb = smem_u32(sm);
    const int tid = threadIdx.x, wid = tid >> 5, lane = tid & 31;
    const int wm = wid >> 2, wn = wid & 3;
    const int b = blockIdx.y, t0 = blockIdx.x * 64;

    // pq / Wscore into smem
    {
        ((float*)(sm + SB_PQ))[tid] = g_projq[b * E_ + tid];
        ((float*)(sm + SB_W))[tid]  = Wscore[tid];
    }

    // loader index split
    const int tx = tid & 15, ry = tid >> 4;   // A: 16 float4-cols x 16 rows
    const int u  = tid & 7,  eb = tid >> 3;   // B: 8 16B-units x 32 e-rows
    const float4* vsrc = (const float4*)(values + ((size_t)b * T_ + t0) * D_);

    // per-lane ldmatrix geometry
    const unsigned arow  = lane & 15;
    const unsigned akoff = (lane >> 4) << 4;          // 0 or 16 bytes
    const unsigned brow  = (lane & 7) + ((lane & 16) >> 1);
    const unsigned bkoff = (lane & 8) << 1;           // 0 or 16 bytes

    float acc[2][8][4];
#pragma unroll
    for (int m = 0; m < 2; m++)
#pragma unroll
        for (int n = 0; n < 8; n++)
#pragma unroll
            for (int i = 0; i < 4; i++) acc[m][n][i] = 0.f;

    // ---- A chunk loader pieces (64 rows x 64 k-floats per chunk) ----
    float4 pv[4];
    auto lda = [&](int c) {
#pragma unroll
        for (int p = 0; p < 4; p++)
            pv[p] = vsrc[(size_t)(ry + 16 * p) * 64 + c * 16 + tx];
    };
    auto sta = [&](int c) {
        char* a = sm + SB_A(c);
#pragma unroll
        for (int p = 0; p < 4; p++) {
            const int row = ry + 16 * p;
            float4 v = pv[p];
            unsigned h01, h23;
            asm("cvt.rn.f16x2.f32 %0, %1, %2;" : "=r"(h01) : "f"(v.y), "f"(v.x));
            asm("cvt.rn.f16x2.f32 %0, %1, %2;" : "=r"(h23) : "f"(v.w), "f"(v.z));
            unsigned off = sw128((unsigned)(row * 128 + tx * 8));
            *(uint2*)(a + off) = make_uint2(h01, h23);
        }
    };
    auto ldb = [&](int c, int s) {
#pragma unroll
        for (int p = 0; p < 8; p++) {
            const int e = eb + 32 * p;
            const unsigned doff = sw128((unsigned)(e * 128 + u * 16));
            cpasync16(sb + SB_B(s) + doff, g_Wvf + (size_t)e * D_ + c * 64 + u * 8);
        }
        cp_commit();
    };

    // prologue: chunk 0 -> A stage 0, B stage 0
    lda(0);
    ldb(0, 0);
    sta(0);
    cp_wait0();
    __syncthreads();

    for (int c = 0; c < 4; c++) {
        const int s = c & 1;
        if (c < 3) {                 // prefetch next chunk
            lda(c + 1);
            ldb(c + 1, s ^ 1);
        }
        // ---- compute chunk c ----
        const unsigned ab = sb + SB_A(c), bb = sb + SB_B(s);
#pragma unroll
        for (int kk = 0; kk < 4; kk++) {
            unsigned A[2][4];
#pragma unroll
            for (int mb = 0; mb < 2; mb++) {
                const unsigned aoff =
                    sw128((wm * 32 + mb * 16 + arow) * 128 + (unsigned)kk * 32 + akoff);
                ldsm4(A[mb], ab + aoff);
            }
#pragma unroll
            for (int g = 0; g < 4; g++) {
                unsigned Bv[4];
                const unsigned boff =
                    sw128((wn * 64 + g * 16 + brow) * 128 + (unsigned)kk * 32 + bkoff);
                ldsm4(Bv, bb + boff);
#pragma unroll
                for (int mb = 0; mb < 2; mb++) {
                    mma16816(acc[mb][2 * g],     A[mb], Bv[0], Bv[1]);
                    mma16816(acc[mb][2 * g + 1], A[mb], Bv[2], Bv[3]);
                }
            }
        }
        if (c < 3) {
            sta(c + 1);
            cp_wait0();
        }
        __syncthreads();
    }

    // ---- epilogue 1: tanh + dot(Wscore) + score + exp-sum ----
    const float* pq = (const float*)(sm + SB_PQ);
    const float* w  = (const float*)(sm + SB_W);
    float* red = (float*)(sm + SB_RED);

    const int c0 = wn * 64 + (lane & 3) * 2;
#pragma unroll
    for (int mb = 0; mb < 2; mb++) {
        float r0 = 0.f, r1 = 0.f;
#pragma unroll
        for (int nb = 0; nb < 8; nb++) {
            const int ca = c0 + nb * 8, cb = ca + 1;
            const float pqa = pq[ca], pqb = pq[cb];
            const float wa = w[ca],  wb = w[cb];
            r0 += fast_tanh(acc[mb][nb][0] + pqa) * wa;
            r0 += fast_tanh(acc[mb][nb][1] + pqb) * wb;
            r1 += fast_tanh(acc[mb][nb][2] + pqa) * wa;
            r1 += fast_tanh(acc[mb][nb][3] + pqb) * wb;
        }
#pragma unroll
        for (int off = 1; off <= 2; off <<= 1) {
            r0 += __shfl_xor_sync(0xffffffffu, r0, off);
            r1 += __shfl_xor_sync(0xffffffffu, r1, off);
        }
        if ((lane & 3) == 0) {
            const int tok = wm * 32 + mb * 16 + (lane >> 2);
            red[tok * 5 + wn]       = r0;
            red[(tok + 8) * 5 + wn] = r1;
        }
    }
    __syncthreads();

    float* wbuf  = (float*)(sm + SB_WB);
    float* sattn = (float*)(sm + SB_SAT);
    if (tid < 64) {
        float s = red[tid * 5] + red[tid * 5 + 1] + red[tid * 5 + 2] + red[tid * 5 + 3];
        g_scores[b * T_ + t0 + tid] = s;
        // unnormalized softmax weight (no max shift: |score| <= ||Wscore||_1 ~ 13)
        float e = __expf(s);
        wbuf[tid] = e;
        float esum = e;
#pragma unroll
        for (int off = 16; off > 0; off >>= 1)
            esum += __shfl_xor_sync(0xffffffffu, esum, off);
        if (lane == 0) atomicAdd(&g_sum[b], esum);
    }
    sattn[tid] = 0.f;
    __syncthreads();

    // ---- epilogue 2: attn partial from resident fp16 A tiles ----
    {
        const int dgrp = tid & 63;         // 64 d-groups of 4
        const int sub  = tid >> 6;         // token subset 0..3
        const int cd   = dgrp >> 4;        // A stage (k-chunk)
        const unsigned col8 = (unsigned)(dgrp & 15) * 8;
        const char* abase = sm + SB_A(cd);
        float a0 = 0.f, a1 = 0.f, a2 = 0.f, a3 = 0.f;
#pragma unroll
        for (int i = 0; i < 16; i++) {
            const int t = sub + i * 4;
            const float wt = wbuf[t];
            uint2 hv = *(const uint2*)(abase + sw128((unsigned)(t * 128) + col8));
            float2 f0 = __half22float2(*reinterpret_cast<__half2*>(&hv.x));
            float2 f1 = __half22float2(*reinterpret_cast<__half2*>(&hv.y));
            a0 = fmaf(wt, f0.x, a0);
            a1 = fmaf(wt, f0.y, a1);
            a2 = fmaf(wt, f1.x, a2);
            a3 = fmaf(wt, f1.y, a3);
        }
        const int d0 = dgrp * 4;
        atomicAdd(&sattn[d0 + 0], a0);
        atomicAdd(&sattn[d0 + 1], a1);
        atomicAdd(&sattn[d0 + 2], a2);
        atomicAdd(&sattn[d0 + 3], a3);
    }
    __syncthreads();
    atomicAdd(&g_attn[b * D_ + tid], sattn[tid]);
}

// ---------------- final: alignments + attentions (normalize) ----------------
__global__ void align_kernel(float* __restrict__ out) {
    const int b = blockIdx.y, t0 = blockIdx.x * 512, tid = threadIdx.x;  // 512 thr
    const float inv = 1.f / g_sum[b];
    const float s = g_scores[(size_t)b * T_ + t0 + tid];
    out[B_ * D_ + (size_t)b * T_ + t0 + tid] = __expf(s) * inv;
    if (blockIdx.x == 0 && tid < D_)
        out[b * D_ + tid] = g_attn[b * D_ + tid] * inv;
}

// ---------------- launch ----------------
extern "C" void kernel_launch(void* const* d_in, const int* in_sizes, int n_in,
                              void* d_out, int out_size) {
    const float* query  = (const float*)d_in[0];
    const float* values = (const float*)d_in[1];
    const float* Wv     = (const float*)d_in[2];
    const float* Wu     = (const float*)d_in[3];
    const float* Wscore = (const float*)d_in[4];
    float* out = (float*)d_out;

    cudaFuncSetAttribute(score_kernel,
                         cudaFuncAttributeMaxDynamicSharedMemorySize, SMEM_TOTAL);

    prep_kernel<<<288, 256>>>(Wv, query, Wu);
    score_kernel<<<dim3(T_ / 64, B_), 256, SMEM_TOTAL>>>(values, Wscore);
    align_kernel<<<dim3(T_ / 512, B_), 512>>>(out);
}

// round 10
// speedup vs baseline: 1.4443x; 1.3107x over previous
#include <cuda_runtime.h>
#include <cuda_fp16.h>

#define B_   32
#define T_   4096
#define D_   256
#define DQ_  512
#define E_   256

// ---------------- scratch (static device globals) ----------------
__device__ float g_scores[B_ * T_];
__device__ float g_projq[B_ * E_];
__device__ float g_sum[B_];
__device__ float g_attn[B_ * D_];                 // unnormalized attention accum
__device__ __align__(16) __half g_Wvf[E_ * D_];   // [e][k] transposed fp16

// ---------------- helpers ----------------
__device__ __forceinline__ unsigned smem_u32(const void* p) {
    unsigned a;
    asm("{ .reg .u64 t; cvta.to.shared.u64 t, %1; cvt.u32.u64 %0, t; }"
        : "=r"(a) : "l"(p));
    return a;
}
__device__ __forceinline__ unsigned sw128(unsigned b) { return b ^ ((b >> 3) & 0x70); }

__device__ __forceinline__ void ldsm4(unsigned r[4], unsigned addr) {
    asm volatile("ldmatrix.sync.aligned.m8n8.x4.shared.b16 {%0,%1,%2,%3}, [%4];"
                 : "=r"(r[0]), "=r"(r[1]), "=r"(r[2]), "=r"(r[3]) : "r"(addr));
}
__device__ __forceinline__ void mma16816(float d[4], const unsigned a[4],
                                         unsigned b0, unsigned b1) {
    asm volatile(
        "mma.sync.aligned.m16n8k16.row.col.f32.f16.f16.f32 "
        "{%0,%1,%2,%3}, {%4,%5,%6,%7}, {%8,%9}, {%0,%1,%2,%3};"
        : "+f"(d[0]), "+f"(d[1]), "+f"(d[2]), "+f"(d[3])
        : "r"(a[0]), "r"(a[1]), "r"(a[2]), "r"(a[3]), "r"(b0), "r"(b1));
}
__device__ __forceinline__ void cpasync16(unsigned dst, const void* src) {
    asm volatile("cp.async.cg.shared.global [%0], [%1], 16;" :: "r"(dst), "l"(src));
}
__device__ __forceinline__ void cp_commit() { asm volatile("cp.async.commit_group;"); }
__device__ __forceinline__ void cp_wait0()  { asm volatile("cp.async.wait_group 0;" ::: "memory"); }

// fast tanh: 1 - 2/(e^{2x}+1); MUFU-based, saturates correctly
__device__ __forceinline__ float fast_tanh(float x) {
    float e = __expf(2.f * x);
    return 1.f - __fdividef(2.f, e + 1.f);
}

// smem layout (bytes):
//   A: 4 stages (one per K-chunk, kept live for the attn epilogue), 8KB each
//   B: 2 stages (double-buffered), 32KB each
#define SB_A(c)     ((c) * 8192)
#define SB_B(s)     (32768 + (s) * 32768)
#define SB_PQ       98304
#define SB_W        99328
#define SB_RED      100352                 // 64*5*4 = 1280
#define SB_WB       101632                 // 64 floats: exp(score)
#define SB_SAT      101888                 // 256 floats: CTA attn partial
#define SMEM_TOTAL  102912

// ---------------- prep: Wv->fp16T (blocks 0-63), proj_q (blocks 64-95) ------
// 1024 threads per block.
__global__ void prep_kernel(const float* __restrict__ Wv,
                            const float* __restrict__ query,
                            const float* __restrict__ Wu) {
    const int blk = blockIdx.x;
    const int tid = threadIdx.x;            // 1024
    if (blk < 64) {
        // Wv split/transpose: 4 k-rows per block
        const int k = blk * 4 + (tid >> 8);
        const int e = tid & 255;
        g_Wvf[e * D_ + k] = __float2half(Wv[k * E_ + e]);
    } else {
        // proj_q for b = blk - 64; 4 K-slices x 256 e
        const int b = blk - 64;
        const int e = tid & 255;
        const int ks = tid >> 8;            // 0..3, k in [128ks, 128ks+128)
        __shared__ float q[DQ_];
        __shared__ float part[4][E_];
        if (tid < DQ_) q[tid] = query[b * DQ_ + tid];
        __syncthreads();
        float acc = 0.f;
        const float* wu = Wu + (size_t)(ks * 128) * E_ + e;
#pragma unroll 8
        for (int k = 0; k < 128; k++)
            acc = fmaf(q[ks * 128 + k], wu[(size_t)k * E_], acc);
        part[ks][e] = acc;
        __syncthreads();
        if (ks == 0) {
            g_projq[b * E_ + e] = part[0][e] + part[1][e] + part[2][e] + part[3][e];
            g_attn[b * D_ + e] = 0.f;
            if (e == 0) g_sum[b] = 0.f;
        }
    }
}

// ---------------- fused: fp16 GEMM + tanh + score + exp-sum + attn partial ----
// 256 threads / 8 warps as 2 m-groups x 4 n-groups; 2 CTAs/SM.
// Tile M=64 tok x N=256 e x K=256. Warp (wm, wn): tokens [32wm,32wm+32),
// e-slice [64wn, 64wn+64). A tiles stay resident (4 stages) for the epilogue.
__global__ void __launch_bounds__(256, 2) score_kernel(
    const float* __restrict__ values,
    const float* __restrict__ Wscore) {

    extern __shared__ char sm[];
    const unsigned sb = smem_u32(sm);
    const int tid = threadIdx.x, wid = tid >> 5, lane = tid & 31;
    const int wm = wid >> 2, wn = wid & 3;
    const int b = blockIdx.y, t0 = blockIdx.x * 64;

    // pq / Wscore into smem
    {
        ((float*)(sm + SB_PQ))[tid] = g_projq[b * E_ + tid];
        ((float*)(sm + SB_W))[tid]  = Wscore[tid];
    }

    // loader index split
    const int tx = tid & 15, ry = tid >> 4;   // A: 16 float4-cols x 16 rows
    const int u  = tid & 7,  eb = tid >> 3;   // B: 8 16B-units x 32 e-rows
    const float4* vsrc = (const float4*)(values + ((size_t)b * T_ + t0) * D_);

    // per-lane ldmatrix geometry
    const unsigned arow  = lane & 15;
    const unsigned akoff = (lane >> 4) << 4;          // 0 or 16 bytes
    const unsigned brow  = (lane & 7) + ((lane & 16) >> 1);
    const unsigned bkoff = (lane & 8) << 1;           // 0 or 16 bytes

    float acc[2][8][4];
#pragma unroll
    for (int m = 0; m < 2; m++)
#pragma unroll
        for (int n = 0; n < 8; n++)
#pragma unroll
            for (int i = 0; i < 4; i++) acc[m][n][i] = 0.f;

    // ---- A chunk loader pieces (64 rows x 64 k-floats per chunk) ----
    float4 pv[4];
    auto lda = [&](int c) {
#pragma unroll
        for (int p = 0; p < 4; p++)
            pv[p] = vsrc[(size_t)(ry + 16 * p) * 64 + c * 16 + tx];
    };
    auto sta = [&](int c) {
        char* a = sm + SB_A(c);
#pragma unroll
        for (int p = 0; p < 4; p++) {
            const int row = ry + 16 * p;
            float4 v = pv[p];
            unsigned h01, h23;
            asm("cvt.rn.f16x2.f32 %0, %1, %2;" : "=r"(h01) : "f"(v.y), "f"(v.x));
            asm("cvt.rn.f16x2.f32 %0, %1, %2;" : "=r"(h23) : "f"(v.w), "f"(v.z));
            unsigned off = sw128((unsigned)(row * 128 + tx * 8));
            *(uint2*)(a + off) = make_uint2(h01, h23);
        }
    };
    auto ldb = [&](int c, int s) {
#pragma unroll
        for (int p = 0; p < 8; p++) {
            const int e = eb + 32 * p;
            const unsigned doff = sw128((unsigned)(e * 128 + u * 16));
            cpasync16(sb + SB_B(s) + doff, g_Wvf + (size_t)e * D_ + c * 64 + u * 8);
        }
        cp_commit();
    };

    // prologue: chunk 0 -> A stage 0, B stage 0
    lda(0);
    ldb(0, 0);
    sta(0);
    cp_wait0();
    __syncthreads();

    for (int c = 0; c < 4; c++) {
        const int s = c & 1;
        if (c < 3) {                 // prefetch next chunk
            lda(c + 1);
            ldb(c + 1, s ^ 1);
        }
        // ---- compute chunk c ----
        const unsigned ab = sb + SB_A(c), bb = sb + SB_B(s);
#pragma unroll
        for (int kk = 0; kk < 4; kk++) {
            unsigned A[2][4];
#pragma unroll
            for (int mb = 0; mb < 2; mb++) {
                const unsigned aoff =
                    sw128((wm * 32 + mb * 16 + arow) * 128 + (unsigned)kk * 32 + akoff);
                ldsm4(A[mb], ab + aoff);
            }
#pragma unroll
            for (int g = 0; g < 4; g++) {
                unsigned Bv[4];
                const unsigned boff =
                    sw128((wn * 64 + g * 16 + brow) * 128 + (unsigned)kk * 32 + bkoff);
                ldsm4(Bv, bb + boff);
#pragma unroll
                for (int mb = 0; mb < 2; mb++) {
                    mma16816(acc[mb][2 * g],     A[mb], Bv[0], Bv[1]);
                    mma16816(acc[mb][2 * g + 1], A[mb], Bv[2], Bv[3]);
                }
            }
        }
        if (c < 3) {
            sta(c + 1);
            cp_wait0();
        }
        __syncthreads();
    }

    // ---- epilogue 1: tanh + dot(Wscore) + score + exp-sum ----
    const float* pq = (const float*)(sm + SB_PQ);
    const float* w  = (const float*)(sm + SB_W);
    float* red = (float*)(sm + SB_RED);

    const int c0 = wn * 64 + (lane & 3) * 2;
#pragma unroll
    for (int mb = 0; mb < 2; mb++) {
        float r0 = 0.f, r1 = 0.f;
#pragma unroll
        for (int nb = 0; nb < 8; nb++) {
            const int ca = c0 + nb * 8, cb = ca + 1;
            const float pqa = pq[ca], pqb = pq[cb];
            const float wa = w[ca],  wb = w[cb];
            r0 += fast_tanh(acc[mb][nb][0] + pqa) * wa;
            r0 += fast_tanh(acc[mb][nb][1] + pqb) * wb;
            r1 += fast_tanh(acc[mb][nb][2] + pqa) * wa;
            r1 += fast_tanh(acc[mb][nb][3] + pqb) * wb;
        }
#pragma unroll
        for (int off = 1; off <= 2; off <<= 1) {
            r0 += __shfl_xor_sync(0xffffffffu, r0, off);
            r1 += __shfl_xor_sync(0xffffffffu, r1, off);
        }
        if ((lane & 3) == 0) {
            const int tok = wm * 32 + mb * 16 + (lane >> 2);
            red[tok * 5 + wn]       = r0;
            red[(tok + 8) * 5 + wn] = r1;
        }
    }
    __syncthreads();

    float* wbuf  = (float*)(sm + SB_WB);
    float* sattn = (float*)(sm + SB_SAT);
    if (tid < 64) {
        float s = red[tid * 5] + red[tid * 5 + 1] + red[tid * 5 + 2] + red[tid * 5 + 3];
        g_scores[b * T_ + t0 + tid] = s;
        // unnormalized softmax weight (no max shift: |score| <= ||Wscore||_1 ~ 13)
        float e = __expf(s);
        wbuf[tid] = e;
        float esum = e;
#pragma unroll
        for (int off = 16; off > 0; off >>= 1)
            esum += __shfl_xor_sync(0xffffffffu, esum, off);
        if (lane == 0) atomicAdd(&g_sum[b], esum);
    }
    sattn[tid] = 0.f;
    __syncthreads();

    // ---- epilogue 2: attn partial from resident fp16 A tiles ----
    {
        const int dgrp = tid & 63;         // 64 d-groups of 4
        const int sub  = tid >> 6;         // token subset 0..3
        const int cd   = dgrp >> 4;        // A stage (k-chunk)
        const unsigned col8 = (unsigned)(dgrp & 15) * 8;
        const char* abase = sm + SB_A(cd);
        float a0 = 0.f, a1 = 0.f, a2 = 0.f, a3 = 0.f;
#pragma unroll
        for (int i = 0; i < 16; i++) {
            const int t = sub + i * 4;
            const float wt = wbuf[t];
            uint2 hv = *(const uint2*)(abase + sw128((unsigned)(t * 128) + col8));
            float2 f0 = __half22float2(*reinterpret_cast<__half2*>(&hv.x));
            float2 f1 = __half22float2(*reinterpret_cast<__half2*>(&hv.y));
            a0 = fmaf(wt, f0.x, a0);
            a1 = fmaf(wt, f0.y, a1);
            a2 = fmaf(wt, f1.x, a2);
            a3 = fmaf(wt, f1.y, a3);
        }
        const int d0 = dgrp * 4;
        atomicAdd(&sattn[d0 + 0], a0);
        atomicAdd(&sattn[d0 + 1], a1);
        atomicAdd(&sattn[d0 + 2], a2);
        atomicAdd(&sattn[d0 + 3], a3);
    }
    __syncthreads();
    atomicAdd(&g_attn[b * D_ + tid], sattn[tid]);
}

// ---------------- final: alignments + attentions (normalize) ----------------
__global__ void align_kernel(float* __restrict__ out) {
    const int b = blockIdx.y, t0 = blockIdx.x * 512, tid = threadIdx.x;  // 512 thr
    const float inv = 1.f / g_sum[b];
    const float s = g_scores[(size_t)b * T_ + t0 + tid];
    out[B_ * D_ + (size_t)b * T_ + t0 + tid] = __expf(s) * inv;
    if (blockIdx.x == 0 && tid < D_)
        out[b * D_ + tid] = g_attn[b * D_ + tid] * inv;
}

// ---------------- launch ----------------
extern "C" void kernel_launch(void* const* d_in, const int* in_sizes, int n_in,
                              void* d_out, int out_size) {
    const float* query  = (const float*)d_in[0];
    const float* values = (const float*)d_in[1];
    const float* Wv     = (const float*)d_in[2];
    const float* Wu     = (const float*)d_in[3];
    const float* Wscore = (const float*)d_in[4];
    float* out = (float*)d_out;

    cudaFuncSetAttribute(score_kernel,
                         cudaFuncAttributeMaxDynamicSharedMemorySize, SMEM_TOTAL);

    prep_kernel<<<96, 1024>>>(Wv, query, Wu);
    score_kernel<<<dim3(T_ / 64, B_), 256, SMEM_TOTAL>>>(values, Wscore);
    align_kernel<<<dim3(T_ / 512, B_), 512>>>(out);
}

// round 12
// speedup vs baseline: 1.4887x; 1.0308x over previous
#include <cuda_runtime.h>
#include <cuda_fp16.h>

#define B_   32
#define T_   4096
#define D_   256
#define DQ_  512
#define E_   256

// ---------------- scratch (static device globals) ----------------
__device__ float g_scores[B_ * T_];
__device__ float g_projq[B_ * E_];
__device__ float g_sum[B_];
__device__ float g_attn[B_ * D_];                 // unnormalized attention accum
__device__ __align__(16) __half g_Wvf[E_ * D_];   // [e][k] transposed fp16

// ---------------- helpers ----------------
__device__ __forceinline__ unsigned smem_u32(const void* p) {
    unsigned a;
    asm("{ .reg .u64 t; cvta.to.shared.u64 t, %1; cvt.u32.u64 %0, t; }"
        : "=r"(a) : "l"(p));
    return a;
}
__device__ __forceinline__ unsigned sw128(unsigned b) { return b ^ ((b >> 3) & 0x70); }

__device__ __forceinline__ void ldsm4(unsigned r[4], unsigned addr) {
    asm volatile("ldmatrix.sync.aligned.m8n8.x4.shared.b16 {%0,%1,%2,%3}, [%4];"
                 : "=r"(r[0]), "=r"(r[1]), "=r"(r[2]), "=r"(r[3]) : "r"(addr));
}
__device__ __forceinline__ void mma16816(float d[4], const unsigned a[4],
                                         unsigned b0, unsigned b1) {
    asm volatile(
        "mma.sync.aligned.m16n8k16.row.col.f32.f16.f16.f32 "
        "{%0,%1,%2,%3}, {%4,%5,%6,%7}, {%8,%9}, {%0,%1,%2,%3};"
        : "+f"(d[0]), "+f"(d[1]), "+f"(d[2]), "+f"(d[3])
        : "r"(a[0]), "r"(a[1]), "r"(a[2]), "r"(a[3]), "r"(b0), "r"(b1));
}
__device__ __forceinline__ void cpasync16(unsigned dst, const void* src) {
    asm volatile("cp.async.cg.shared.global [%0], [%1], 16;" :: "r"(dst), "l"(src));
}
__device__ __forceinline__ void cp_commit() { asm volatile("cp.async.commit_group;"); }
__device__ __forceinline__ void cp_wait0()  { asm volatile("cp.async.wait_group 0;" ::: "memory"); }

// fast tanh: 1 - 2/(e^{2x}+1); MUFU-based, saturates correctly
__device__ __forceinline__ float fast_tanh(float x) {
    float e = __expf(2.f * x);
    return 1.f - __fdividef(2.f, e + 1.f);
}

// smem layout (bytes):
//   A: 4 stages (one per K-chunk, kept live for the attn epilogue), 8KB each
//   B: 2 stages (double-buffered), 32KB each
#define SB_A(c)     ((c) * 8192)
#define SB_B(s)     (32768 + (s) * 32768)
#define SB_PQ       98304
#define SB_W        99328
#define SB_RED      100352                 // 64*5*4 = 1280
#define SB_WB       101632                 // 64 floats: exp(score)
#define SB_SAT      101888                 // 256 floats: CTA attn partial
#define SMEM_TOTAL  102912

// ---------------- prep: Wv->fp16T (blocks 0-63), proj_q (blocks 64-95) ------
// 1024 threads per block. projq uses 4 independent accumulators + bounded
// unroll so ptxas batches the Wu loads (MLP ~32) instead of one serial chain.
__global__ void prep_kernel(const float* __restrict__ Wv,
                            const float* __restrict__ query,
                            const float* __restrict__ Wu) {
    const int blk = blockIdx.x;
    const int tid = threadIdx.x;            // 1024
    if (blk < 64) {
        // Wv split/transpose: 4 k-rows per block
        const int k = blk * 4 + (tid >> 8);
        const int e = tid & 255;
        g_Wvf[e * D_ + k] = __float2half(Wv[k * E_ + e]);
    } else {
        // proj_q for b = blk - 64; 4 K-slices x 256 e
        const int b = blk - 64;
        const int e = tid & 255;
        const int ks = tid >> 8;            // 0..3, k in [128ks, 128ks+128)
        __shared__ float q[DQ_];
        __shared__ float part[4][E_];
        if (tid < DQ_) q[tid] = query[b * DQ_ + tid];
        __syncthreads();
        float a0 = 0.f, a1 = 0.f, a2 = 0.f, a3 = 0.f;
        const float* qk = q + ks * 128;
        const float* wu = Wu + (size_t)(ks * 128) * E_ + e;
#pragma unroll 8
        for (int k = 0; k < 128; k += 4) {
            a0 = fmaf(qk[k],     wu[(size_t)(k)     * E_], a0);
            a1 = fmaf(qk[k + 1], wu[(size_t)(k + 1) * E_], a1);
            a2 = fmaf(qk[k + 2], wu[(size_t)(k + 2) * E_], a2);
            a3 = fmaf(qk[k + 3], wu[(size_t)(k + 3) * E_], a3);
        }
        part[ks][e] = (a0 + a1) + (a2 + a3);
        __syncthreads();
        if (ks == 0) {
            g_projq[b * E_ + e] = part[0][e] + part[1][e] + part[2][e] + part[3][e];
            g_attn[b * D_ + e] = 0.f;
            if (e == 0) g_sum[b] = 0.f;
        }
    }
}

// ---------------- fused: fp16 GEMM + tanh + score + exp-sum + attn partial ----
// 256 threads / 8 warps as 2 m-groups x 4 n-groups; 2 CTAs/SM.
// Tile M=64 tok x N=256 e x K=256. Warp (wm, wn): tokens [32wm,32wm+32),
// e-slice [64wn, 64wn+64). A tiles stay resident (4 stages) for the epilogue.
__global__ void __launch_bounds__(256, 2) score_kernel(
    const float* __restrict__ values,
    const float* __restrict__ Wscore) {

    extern __shared__ char sm[];
    const unsigned sb = smem_u32(sm);
    const int tid = threadIdx.x, wid = tid >> 5, lane = tid & 31;
    const int wm = wid >> 2, wn = wid & 3;
    const int b = blockIdx.y, t0 = blockIdx.x * 64;

    // pq / Wscore into smem
    {
        ((float*)(sm + SB_PQ))[tid] = g_projq[b * E_ + tid];
        ((float*)(sm + SB_W))[tid]  = Wscore[tid];
    }

    // loader index split
    const int tx = tid & 15, ry = tid >> 4;   // A: 16 float4-cols x 16 rows
    const int u  = tid & 7,  eb = tid >> 3;   // B: 8 16B-units x 32 e-rows
    const float4* vsrc = (const float4*)(values + ((size_t)b * T_ + t0) * D_);

    // per-lane ldmatrix geometry
    const unsigned arow  = lane & 15;
    const unsigned akoff = (lane >> 4) << 4;          // 0 or 16 bytes
    const unsigned brow  = (lane & 7) + ((lane & 16) >> 1);
    const unsigned bkoff = (lane & 8) << 1;           // 0 or 16 bytes

    float acc[2][8][4];
#pragma unroll
    for (int m = 0; m < 2; m++)
#pragma unroll
        for (int n = 0; n < 8; n++)
#pragma unroll
            for (int i = 0; i < 4; i++) acc[m][n][i] = 0.f;

    // ---- A chunk loader pieces (64 rows x 64 k-floats per chunk) ----
    float4 pv[4];
    auto lda = [&](int c) {
#pragma unroll
        for (int p = 0; p < 4; p++)
            pv[p] = vsrc[(size_t)(ry + 16 * p) * 64 + c * 16 + tx];
    };
    auto sta = [&](int c) {
        char* a = sm + SB_A(c);
#pragma unroll
        for (int p = 0; p < 4; p++) {
            const int row = ry + 16 * p;
            float4 v = pv[p];
            unsigned h01, h23;
            asm("cvt.rn.f16x2.f32 %0, %1, %2;" : "=r"(h01) : "f"(v.y), "f"(v.x));
            asm("cvt.rn.f16x2.f32 %0, %1, %2;" : "=r"(h23) : "f"(v.w), "f"(v.z));
            unsigned off = sw128((unsigned)(row * 128 + tx * 8));
            *(uint2*)(a + off) = make_uint2(h01, h23);
        }
    };
    auto ldb = [&](int c, int s) {
#pragma unroll
        for (int p = 0; p < 8; p++) {
            const int e = eb + 32 * p;
            const unsigned doff = sw128((unsigned)(e * 128 + u * 16));
            cpasync16(sb + SB_B(s) + doff, g_Wvf + (size_t)e * D_ + c * 64 + u * 8);
        }
        cp_commit();
    };

    // prologue: chunk 0 -> A stage 0, B stage 0
    lda(0);
    ldb(0, 0);
    sta(0);
    cp_wait0();
    __syncthreads();

    for (int c = 0; c < 4; c++) {
        const int s = c & 1;
        if (c < 3) {                 // prefetch next chunk
            lda(c + 1);
            ldb(c + 1, s ^ 1);
        }
        // ---- compute chunk c ----
        const unsigned ab = sb + SB_A(c), bb = sb + SB_B(s);
#pragma unroll
        for (int kk = 0; kk < 4; kk++) {
            unsigned A[2][4];
#pragma unroll
            for (int mb = 0; mb < 2; mb++) {
                const unsigned aoff =
                    sw128((wm * 32 + mb * 16 + arow) * 128 + (unsigned)kk * 32 + akoff);
                ldsm4(A[mb], ab + aoff);
            }
#pragma unroll
            for (int g = 0; g < 4; g++) {
                unsigned Bv[4];
                const unsigned boff =
                    sw128((wn * 64 + g * 16 + brow) * 128 + (unsigned)kk * 32 + bkoff);
                ldsm4(Bv, bb + boff);
#pragma unroll
                for (int mb = 0; mb < 2; mb++) {
                    mma16816(acc[mb][2 * g],     A[mb], Bv[0], Bv[1]);
                    mma16816(acc[mb][2 * g + 1], A[mb], Bv[2], Bv[3]);
                }
            }
        }
        if (c < 3) {
            sta(c + 1);
            cp_wait0();
        }
        __syncthreads();
    }

    // ---- epilogue 1: tanh + dot(Wscore) + score + exp-sum ----
    const float* pq = (const float*)(sm + SB_PQ);
    const float* w  = (const float*)(sm + SB_W);
    float* red = (float*)(sm + SB_RED);

    const int c0 = wn * 64 + (lane & 3) * 2;
#pragma unroll
    for (int mb = 0; mb < 2; mb++) {
        float r0 = 0.f, r1 = 0.f;
#pragma unroll
        for (int nb = 0; nb < 8; nb++) {
            const int ca = c0 + nb * 8, cb = ca + 1;
            const float pqa = pq[ca], pqb = pq[cb];
            const float wa = w[ca],  wb = w[cb];
            r0 += fast_tanh(acc[mb][nb][0] + pqa) * wa;
            r0 += fast_tanh(acc[mb][nb][1] + pqb) * wb;
            r1 += fast_tanh(acc[mb][nb][2] + pqa) * wa;
            r1 += fast_tanh(acc[mb][nb][3] + pqb) * wb;
        }
#pragma unroll
        for (int off = 1; off <= 2; off <<= 1) {
            r0 += __shfl_xor_sync(0xffffffffu, r0, off);
            r1 += __shfl_xor_sync(0xffffffffu, r1, off);
        }
        if ((lane & 3) == 0) {
            const int tok = wm * 32 + mb * 16 + (lane >> 2);
            red[tok * 5 + wn]       = r0;
            red[(tok + 8) * 5 + wn] = r1;
        }
    }
    __syncthreads();

    float* wbuf  = (float*)(sm + SB_WB);
    float* sattn = (float*)(sm + SB_SAT);
    if (tid < 64) {
        float s = red[tid * 5] + red[tid * 5 + 1] + red[tid * 5 + 2] + red[tid * 5 + 3];
        g_scores[b * T_ + t0 + tid] = s;
        // unnormalized softmax weight (no max shift: |score| <= ||Wscore||_1 ~ 13)
        float e = __expf(s);
        wbuf[tid] = e;
        float esum = e;
#pragma unroll
        for (int off = 16; off > 0; off >>= 1)
            esum += __shfl_xor_sync(0xffffffffu, esum, off);
        if (lane == 0) atomicAdd(&g_sum[b], esum);
    }
    sattn[tid] = 0.f;
    __syncthreads();

    // ---- epilogue 2: attn partial from resident fp16 A tiles ----
    {
        const int dgrp = tid & 63;         // 64 d-groups of 4
        const int sub  = tid >> 6;         // token subset 0..3
        const int cd   = dgrp >> 4;        // A stage (k-chunk)
        const unsigned col8 = (unsigned)(dgrp & 15) * 8;
        const char* abase = sm + SB_A(cd);
        float a0 = 0.f, a1 = 0.f, a2 = 0.f, a3 = 0.f;
#pragma unroll
        for (int i = 0; i < 16; i++) {
            const int t = sub + i * 4;
            const float wt = wbuf[t];
            uint2 hv = *(const uint2*)(abase + sw128((unsigned)(t * 128) + col8));
            float2 f0 = __half22float2(*reinterpret_cast<__half2*>(&hv.x));
            float2 f1 = __half22float2(*reinterpret_cast<__half2*>(&hv.y));
            a0 = fmaf(wt, f0.x, a0);
            a1 = fmaf(wt, f0.y, a1);
            a2 = fmaf(wt, f1.x, a2);
            a3 = fmaf(wt, f1.y, a3);
        }
        const int d0 = dgrp * 4;
        atomicAdd(&sattn[d0 + 0], a0);
        atomicAdd(&sattn[d0 + 1], a1);
        atomicAdd(&sattn[d0 + 2], a2);
        atomicAdd(&sattn[d0 + 3], a3);
    }
    __syncthreads();
    atomicAdd(&g_attn[b * D_ + tid], sattn[tid]);
}

// ---------------- final: alignments + attentions (normalize) ----------------
__global__ void align_kernel(float* __restrict__ out) {
    const int b = blockIdx.y, t0 = blockIdx.x * 512, tid = threadIdx.x;  // 512 thr
    const float inv = 1.f / g_sum[b];
    const float s = g_scores[(size_t)b * T_ + t0 + tid];
    out[B_ * D_ + (size_t)b * T_ + t0 + tid] = __expf(s) * inv;
    if (blockIdx.x == 0 && tid < D_)
        out[b * D_ + tid] = g_attn[b * D_ + tid] * inv;
}

// ---------------- launch ----------------
extern "C" void kernel_launch(void* const* d_in, const int* in_sizes, int n_in,
                              void* d_out, int out_size) {
    const float* query  = (const float*)d_in[0];
    const float* values = (const float*)d_in[1];
    const float* Wv     = (const float*)d_in[2];
    const float* Wu     = (const float*)d_in[3];
    const float* Wscore = (const float*)d_in[4];
    float* out = (float*)d_out;

    cudaFuncSetAttribute(score_kernel,
                         cudaFuncAttributeMaxDynamicSharedMemorySize, SMEM_TOTAL);

    prep_kernel<<<96, 1024>>>(Wv, query, Wu);
    score_kernel<<<dim3(T_ / 64, B_), 256, SMEM_TOTAL>>>(values, Wscore);
    align_kernel<<<dim3(T_ / 512, B_), 512>>>(out);
}

// round 13
// speedup vs baseline: 1.6203x; 1.0884x over previous
#include <cuda_runtime.h>
#include <cuda_fp16.h>

#define B_   32
#define T_   4096
#define D_   256
#define DQ_  512
#define E_   256

// ---------------- scratch (static device globals) ----------------
__device__ float g_scores[B_ * T_];
__device__ float g_projq[B_ * E_];
__device__ float g_sum[B_];
__device__ float g_attn[B_ * D_];                 // unnormalized attention accum
__device__ __align__(16) __half g_Wvf[E_ * D_];   // [e][k] transposed fp16

// ---------------- helpers ----------------
__device__ __forceinline__ unsigned smem_u32(const void* p) {
    unsigned a;
    asm("{ .reg .u64 t; cvta.to.shared.u64 t, %1; cvt.u32.u64 %0, t; }"
        : "=r"(a) : "l"(p));
    return a;
}
__device__ __forceinline__ unsigned sw128(unsigned b) { return b ^ ((b >> 3) & 0x70); }

__device__ __forceinline__ void ldsm4(unsigned r[4], unsigned addr) {
    asm volatile("ldmatrix.sync.aligned.m8n8.x4.shared.b16 {%0,%1,%2,%3}, [%4];"
                 : "=r"(r[0]), "=r"(r[1]), "=r"(r[2]), "=r"(r[3]) : "r"(addr));
}
__device__ __forceinline__ void mma16816(float d[4], const unsigned a[4],
                                         unsigned b0, unsigned b1) {
    asm volatile(
        "mma.sync.aligned.m16n8k16.row.col.f32.f16.f16.f32 "
        "{%0,%1,%2,%3}, {%4,%5,%6,%7}, {%8,%9}, {%0,%1,%2,%3};"
        : "+f"(d[0]), "+f"(d[1]), "+f"(d[2]), "+f"(d[3])
        : "r"(a[0]), "r"(a[1]), "r"(a[2]), "r"(a[3]), "r"(b0), "r"(b1));
}
__device__ __forceinline__ void cpasync16(unsigned dst, const void* src) {
    asm volatile("cp.async.cg.shared.global [%0], [%1], 16;" :: "r"(dst), "l"(src));
}
__device__ __forceinline__ void cp_commit() { asm volatile("cp.async.commit_group;"); }
__device__ __forceinline__ void cp_wait0()  { asm volatile("cp.async.wait_group 0;" ::: "memory"); }

// single-MUFU tanh (MUFU.TANH, sm_75+)
__device__ __forceinline__ float fast_tanh(float x) {
    float y;
    asm("tanh.approx.f32 %0, %1;" : "=f"(y) : "f"(x));
    return y;
}

// smem layout (bytes):
//   A: 4 stages (one per K-chunk, kept live for the attn epilogue), 8KB each
//   B: 2 stages (double-buffered), 32KB each
#define SB_A(c)     ((c) * 8192)
#define SB_B(s)     (32768 + (s) * 32768)
#define SB_PQ       98304
#define SB_W        99328
#define SB_RED      100352                 // 64*5*4 = 1280
#define SB_WB       101632                 // 64 floats: exp(score)
#define SB_SAT      101888                 // 256 floats: CTA attn partial
#define SMEM_TOTAL  102912

// ---------------- prep: Wv->fp16T (blocks 0-7), proj_q (blocks 8-39) --------
// 1024 threads per block.
// Transpose: thread = (e, 8 consecutive k): 8 coalesced reads (warp spans e),
// one 16B uint4 store of 8 packed halves -> 8x fewer store transactions.
__global__ void prep_kernel(const float* __restrict__ Wv,
                            const float* __restrict__ query,
                            const float* __restrict__ Wu) {
    const int blk = blockIdx.x;
    const int tid = threadIdx.x;            // 1024
    if (blk < 8) {
        const int e  = tid & 255;
        const int k0 = (blk * 4 + (tid >> 8)) * 8;
        float v[8];
#pragma unroll
        for (int j = 0; j < 8; j++)
            v[j] = Wv[(size_t)(k0 + j) * E_ + e];
        unsigned p0, p1, p2, p3;
        asm("cvt.rn.f16x2.f32 %0, %1, %2;" : "=r"(p0) : "f"(v[1]), "f"(v[0]));
        asm("cvt.rn.f16x2.f32 %0, %1, %2;" : "=r"(p1) : "f"(v[3]), "f"(v[2]));
        asm("cvt.rn.f16x2.f32 %0, %1, %2;" : "=r"(p2) : "f"(v[5]), "f"(v[4]));
        asm("cvt.rn.f16x2.f32 %0, %1, %2;" : "=r"(p3) : "f"(v[7]), "f"(v[6]));
        *(uint4*)((char*)g_Wvf + ((size_t)e * D_ + k0) * 2) =
            make_uint4(p0, p1, p2, p3);
    } else {
        // proj_q for b = blk - 8; 4 K-slices x 256 e
        const int b = blk - 8;
        const int e = tid & 255;
        const int ks = tid >> 8;            // 0..3, k in [128ks, 128ks+128)
        __shared__ float q[DQ_];
        __shared__ float part[4][E_];
        if (tid < DQ_) q[tid] = query[b * DQ_ + tid];
        __syncthreads();
        float a0 = 0.f, a1 = 0.f, a2 = 0.f, a3 = 0.f;
        const float* qk = q + ks * 128;
        const float* wu = Wu + (size_t)(ks * 128) * E_ + e;
#pragma unroll 8
        for (int k = 0; k < 128; k += 4) {
            a0 = fmaf(qk[k],     wu[(size_t)(k)     * E_], a0);
            a1 = fmaf(qk[k + 1], wu[(size_t)(k + 1) * E_], a1);
            a2 = fmaf(qk[k + 2], wu[(size_t)(k + 2) * E_], a2);
            a3 = fmaf(qk[k + 3], wu[(size_t)(k + 3) * E_], a3);
        }
        part[ks][e] = (a0 + a1) + (a2 + a3);
        __syncthreads();
        if (ks == 0) {
            g_projq[b * E_ + e] = part[0][e] + part[1][e] + part[2][e] + part[3][e];
            g_attn[b * D_ + e] = 0.f;
            if (e == 0) g_sum[b] = 0.f;
        }
    }
}

// ---------------- fused: fp16 GEMM + tanh + score + exp-sum + attn partial ----
// 256 threads / 8 warps as 2 m-groups x 4 n-groups; 2 CTAs/SM.
// Tile M=64 tok x N=256 e x K=256. Warp (wm, wn): tokens [32wm,32wm+32),
// e-slice [64wn, 64wn+64). A tiles stay resident (4 stages) for the epilogue.
__global__ void __launch_bounds__(256, 2) score_kernel(
    const float* __restrict__ values,
    const float* __restrict__ Wscore) {

    extern __shared__ char sm[];
    const unsigned sb = smem_u32(sm);
    const int tid = threadIdx.x, wid = tid >> 5, lane = tid & 31;
    const int wm = wid >> 2, wn = wid & 3;
    const int b = blockIdx.y, t0 = blockIdx.x * 64;

    // pq / Wscore into smem
    {
        ((float*)(sm + SB_PQ))[tid] = g_projq[b * E_ + tid];
        ((float*)(sm + SB_W))[tid]  = Wscore[tid];
    }

    // loader index split
    const int tx = tid & 15, ry = tid >> 4;   // A: 16 float4-cols x 16 rows
    const int u  = tid & 7,  eb = tid >> 3;   // B: 8 16B-units x 32 e-rows
    const float4* vsrc = (const float4*)(values + ((size_t)b * T_ + t0) * D_);

    // per-lane ldmatrix geometry
    const unsigned arow  = lane & 15;
    const unsigned akoff = (lane >> 4) << 4;          // 0 or 16 bytes
    const unsigned brow  = (lane & 7) + ((lane & 16) >> 1);
    const unsigned bkoff = (lane & 8) << 1;           // 0 or 16 bytes

    float acc[2][8][4];
#pragma unroll
    for (int m = 0; m < 2; m++)
#pragma unroll
        for (int n = 0; n < 8; n++)
#pragma unroll
            for (int i = 0; i < 4; i++) acc[m][n][i] = 0.f;

    // ---- A chunk loader pieces (64 rows x 64 k-floats per chunk) ----
    float4 pv[4];
    auto lda = [&](int c) {
#pragma unroll
        for (int p = 0; p < 4; p++)
            pv[p] = vsrc[(size_t)(ry + 16 * p) * 64 + c * 16 + tx];
    };
    auto sta = [&](int c) {
        char* a = sm + SB_A(c);
#pragma unroll
        for (int p = 0; p < 4; p++) {
            const int row = ry + 16 * p;
            float4 v = pv[p];
            unsigned h01, h23;
            asm("cvt.rn.f16x2.f32 %0, %1, %2;" : "=r"(h01) : "f"(v.y), "f"(v.x));
            asm("cvt.rn.f16x2.f32 %0, %1, %2;" : "=r"(h23) : "f"(v.w), "f"(v.z));
            unsigned off = sw128((unsigned)(row * 128 + tx * 8));
            *(uint2*)(a + off) = make_uint2(h01, h23);
        }
    };
    auto ldb = [&](int c, int s) {
#pragma unroll
        for (int p = 0; p < 8; p++) {
            const int e = eb + 32 * p;
            const unsigned doff = sw128((unsigned)(e * 128 + u * 16));
            cpasync16(sb + SB_B(s) + doff, g_Wvf + (size_t)e * D_ + c * 64 + u * 8);
        }
        cp_commit();
    };

    // prologue: chunk 0 -> A stage 0, B stage 0
    lda(0);
    ldb(0, 0);
    sta(0);
    cp_wait0();
    __syncthreads();

    for (int c = 0; c < 4; c++) {
        const int s = c & 1;
        if (c < 3) {                 // prefetch next chunk
            lda(c + 1);
            ldb(c + 1, s ^ 1);
        }
        // ---- compute chunk c ----
        const unsigned ab = sb + SB_A(c), bb = sb + SB_B(s);
#pragma unroll
        for (int kk = 0; kk < 4; kk++) {
            unsigned A[2][4];
#pragma unroll
            for (int mb = 0; mb < 2; mb++) {
                const unsigned aoff =
                    sw128((wm * 32 + mb * 16 + arow) * 128 + (unsigned)kk * 32 + akoff);
                ldsm4(A[mb], ab + aoff);
            }
#pragma unroll
            for (int g = 0; g < 4; g++) {
                unsigned Bv[4];
                const unsigned boff =
                    sw128((wn * 64 + g * 16 + brow) * 128 + (unsigned)kk * 32 + bkoff);
                ldsm4(Bv, bb + boff);
#pragma unroll
                for (int mb = 0; mb < 2; mb++) {
                    mma16816(acc[mb][2 * g],     A[mb], Bv[0], Bv[1]);
                    mma16816(acc[mb][2 * g + 1], A[mb], Bv[2], Bv[3]);
                }
            }
        }
        if (c < 3) {
            sta(c + 1);
            cp_wait0();
        }
        __syncthreads();
    }

    // ---- epilogue 1: tanh + dot(Wscore) + score + exp-sum ----
    const float* pq = (const float*)(sm + SB_PQ);
    const float* w  = (const float*)(sm + SB_W);
    float* red = (float*)(sm + SB_RED);

    const int c0 = wn * 64 + (lane & 3) * 2;
#pragma unroll
    for (int mb = 0; mb < 2; mb++) {
        float r0 = 0.f, r1 = 0.f;
#pragma unroll
        for (int nb = 0; nb < 8; nb++) {
            const int ca = c0 + nb * 8, cb = ca + 1;
            const float pqa = pq[ca], pqb = pq[cb];
            const float wa = w[ca],  wb = w[cb];
            r0 += fast_tanh(acc[mb][nb][0] + pqa) * wa;
            r0 += fast_tanh(acc[mb][nb][1] + pqb) * wb;
            r1 += fast_tanh(acc[mb][nb][2] + pqa) * wa;
            r1 += fast_tanh(acc[mb][nb][3] + pqb) * wb;
        }
#pragma unroll
        for (int off = 1; off <= 2; off <<= 1) {
            r0 += __shfl_xor_sync(0xffffffffu, r0, off);
            r1 += __shfl_xor_sync(0xffffffffu, r1, off);
        }
        if ((lane & 3) == 0) {
            const int tok = wm * 32 + mb * 16 + (lane >> 2);
            red[tok * 5 + wn]       = r0;
            red[(tok + 8) * 5 + wn] = r1;
        }
    }
    __syncthreads();

    float* wbuf  = (float*)(sm + SB_WB);
    float* sattn = (float*)(sm + SB_SAT);
    if (tid < 64) {
        float s = red[tid * 5] + red[tid * 5 + 1] + red[tid * 5 + 2] + red[tid * 5 + 3];
        g_scores[b * T_ + t0 + tid] = s;
        // unnormalized softmax weight (no max shift: |score| <= ||Wscore||_1 ~ 13)
        float e = __expf(s);
        wbuf[tid] = e;
        float esum = e;
#pragma unroll
        for (int off = 16; off > 0; off >>= 1)
            esum += __shfl_xor_sync(0xffffffffu, esum, off);
        if (lane == 0) atomicAdd(&g_sum[b], esum);
    }
    sattn[tid] = 0.f;
    __syncthreads();

    // ---- epilogue 2: attn partial from resident fp16 A tiles ----
    {
        const int dgrp = tid & 63;         // 64 d-groups of 4
        const int sub  = tid >> 6;         // token subset 0..3
        const int cd   = dgrp >> 4;        // A stage (k-chunk)
        const unsigned col8 = (unsigned)(dgrp & 15) * 8;
        const char* abase = sm + SB_A(cd);
        float a0 = 0.f, a1 = 0.f, a2 = 0.f, a3 = 0.f;
#pragma unroll
        for (int i = 0; i < 16; i++) {
            const int t = sub + i * 4;
            const float wt = wbuf[t];
            uint2 hv = *(const uint2*)(abase + sw128((unsigned)(t * 128) + col8));
            float2 f0 = __half22float2(*reinterpret_cast<__half2*>(&hv.x));
            float2 f1 = __half22float2(*reinterpret_cast<__half2*>(&hv.y));
            a0 = fmaf(wt, f0.x, a0);
            a1 = fmaf(wt, f0.y, a1);
            a2 = fmaf(wt, f1.x, a2);
            a3 = fmaf(wt, f1.y, a3);
        }
        const int d0 = dgrp * 4;
        atomicAdd(&sattn[d0 + 0], a0);
        atomicAdd(&sattn[d0 + 1], a1);
        atomicAdd(&sattn[d0 + 2], a2);
        atomicAdd(&sattn[d0 + 3], a3);
    }
    __syncthreads();
    atomicAdd(&g_attn[b * D_ + tid], sattn[tid]);
}

// ---------------- final: alignments + attentions (normalize) ----------------
__global__ void align_kernel(float* __restrict__ out) {
    const int b = blockIdx.y, t0 = blockIdx.x * 512, tid = threadIdx.x;  // 512 thr
    const float inv = 1.f / g_sum[b];
    const float s = g_scores[(size_t)b * T_ + t0 + tid];
    out[B_ * D_ + (size_t)b * T_ + t0 + tid] = __expf(s) * inv;
    if (blockIdx.x == 0 && tid < D_)
        out[b * D_ + tid] = g_attn[b * D_ + tid] * inv;
}

// ---------------- launch ----------------
extern "C" void kernel_launch(void* const* d_in, const int* in_sizes, int n_in,
                              void* d_out, int out_size) {
    const float* query  = (const float*)d_in[0];
    const float* values = (const float*)d_in[1];
    const float* Wv     = (const float*)d_in[2];
    const float* Wu     = (const float*)d_in[3];
    const float* Wscore = (const float*)d_in[4];
    float* out = (float*)d_out;

    cudaFuncSetAttribute(score_kernel,
                         cudaFuncAttributeMaxDynamicSharedMemorySize, SMEM_TOTAL);

    prep_kernel<<<40, 1024>>>(Wv, query, Wu);
    score_kernel<<<dim3(T_ / 64, B_), 256, SMEM_TOTAL>>>(values, Wscore);
    align_kernel<<<dim3(T_ / 512, B_), 512>>>(out);
}

// round 16
// speedup vs baseline: 1.6254x; 1.0031x over previous
#include <cuda_runtime.h>
#include <cuda_fp16.h>

#define B_   32
#define T_   4096
#define D_   256
#define DQ_  512
#define E_   256

// ---------------- scratch (static device globals) ----------------
__device__ float g_scores[B_ * T_];
__device__ float g_projq[B_ * E_];
__device__ float g_sum[B_];
__device__ float g_attn[B_ * D_];                 // unnormalized attention accum
__device__ __align__(16) __half g_Wvf[E_ * D_];   // [e][k] transposed fp16

// ---------------- helpers ----------------
__device__ __forceinline__ unsigned smem_u32(const void* p) {
    unsigned a;
    asm("{ .reg .u64 t; cvta.to.shared.u64 t, %1; cvt.u32.u64 %0, t; }"
        : "=r"(a) : "l"(p));
    return a;
}
__device__ __forceinline__ unsigned sw128(unsigned b) { return b ^ ((b >> 3) & 0x70); }

__device__ __forceinline__ void ldsm4(unsigned r[4], unsigned addr) {
    asm volatile("ldmatrix.sync.aligned.m8n8.x4.shared.b16 {%0,%1,%2,%3}, [%4];"
                 : "=r"(r[0]), "=r"(r[1]), "=r"(r[2]), "=r"(r[3]) : "r"(addr));
}
__device__ __forceinline__ void mma16816(float d[4], const unsigned a[4],
                                         unsigned b0, unsigned b1) {
    asm volatile(
        "mma.sync.aligned.m16n8k16.row.col.f32.f16.f16.f32 "
        "{%0,%1,%2,%3}, {%4,%5,%6,%7}, {%8,%9}, {%0,%1,%2,%3};"
        : "+f"(d[0]), "+f"(d[1]), "+f"(d[2]), "+f"(d[3])
        : "r"(a[0]), "r"(a[1]), "r"(a[2]), "r"(a[3]), "r"(b0), "r"(b1));
}
__device__ __forceinline__ void cpasync16(unsigned dst, const void* src) {
    asm volatile("cp.async.cg.shared.global [%0], [%1], 16;" :: "r"(dst), "l"(src));
}
__device__ __forceinline__ void cp_commit() { asm volatile("cp.async.commit_group;"); }
__device__ __forceinline__ void cp_wait0()  { asm volatile("cp.async.wait_group 0;" ::: "memory"); }

// single-MUFU tanh (MUFU.TANH, sm_75+)
__device__ __forceinline__ float fast_tanh(float x) {
    float y;
    asm("tanh.approx.f32 %0, %1;" : "=f"(y) : "f"(x));
    return y;
}

// smem layout (bytes):
//   A: 4 stages (one per K-chunk, kept live for the attn epilogue), 8KB each
//   B: 2 stages (double-buffered), 32KB each
#define SB_A(c)     ((c) * 8192)
#define SB_B(s)     (32768 + (s) * 32768)
#define SB_PQ       98304
#define SB_W        99328
#define SB_RED      100352                 // 64*5*4 = 1280
#define SB_WB       101632                 // 64 floats: exp(score)
#define SB_SAT      101888                 // 256 floats: CTA attn partial
#define SMEM_TOTAL  102912

// ---------------- prep: Wv->fp16T (blocks 0-7), proj_q (blocks 8-39) --------
// 1024 threads per block.
// Transpose: thread = (e, 8 consecutive k): 8 coalesced reads (warp spans e),
// one 16B uint4 store of 8 packed halves -> 8x fewer store transactions.
__global__ void prep_kernel(const float* __restrict__ Wv,
                            const float* __restrict__ query,
                            const float* __restrict__ Wu) {
    const int blk = blockIdx.x;
    const int tid = threadIdx.x;            // 1024
    if (blk < 8) {
        const int e  = tid & 255;
        const int k0 = (blk * 4 + (tid >> 8)) * 8;
        float v[8];
#pragma unroll
        for (int j = 0; j < 8; j++)
            v[j] = Wv[(size_t)(k0 + j) * E_ + e];
        unsigned p0, p1, p2, p3;
        asm("cvt.rn.f16x2.f32 %0, %1, %2;" : "=r"(p0) : "f"(v[1]), "f"(v[0]));
        asm("cvt.rn.f16x2.f32 %0, %1, %2;" : "=r"(p1) : "f"(v[3]), "f"(v[2]));
        asm("cvt.rn.f16x2.f32 %0, %1, %2;" : "=r"(p2) : "f"(v[5]), "f"(v[4]));
        asm("cvt.rn.f16x2.f32 %0, %1, %2;" : "=r"(p3) : "f"(v[7]), "f"(v[6]));
        *(uint4*)((char*)g_Wvf + ((size_t)e * D_ + k0) * 2) =
            make_uint4(p0, p1, p2, p3);
    } else {
        // proj_q for b = blk - 8; 4 K-slices x 256 e
        const int b = blk - 8;
        const int e = tid & 255;
        const int ks = tid >> 8;            // 0..3, k in [128ks, 128ks+128)
        __shared__ float q[DQ_];
        __shared__ float part[4][E_];
        if (tid < DQ_) q[tid] = query[b * DQ_ + tid];
        __syncthreads();
        float a0 = 0.f, a1 = 0.f, a2 = 0.f, a3 = 0.f;
        const float* qk = q + ks * 128;
        const float* wu = Wu + (size_t)(ks * 128) * E_ + e;
#pragma unroll 8
        for (int k = 0; k < 128; k += 4) {
            a0 = fmaf(qk[k],     wu[(size_t)(k)     * E_], a0);
            a1 = fmaf(qk[k + 1], wu[(size_t)(k + 1) * E_], a1);
            a2 = fmaf(qk[k + 2], wu[(size_t)(k + 2) * E_], a2);
            a3 = fmaf(qk[k + 3], wu[(size_t)(k + 3) * E_], a3);
        }
        part[ks][e] = (a0 + a1) + (a2 + a3);
        __syncthreads();
        if (ks == 0) {
            g_projq[b * E_ + e] = part[0][e] + part[1][e] + part[2][e] + part[3][e];
            g_attn[b * D_ + e] = 0.f;
            if (e == 0) g_sum[b] = 0.f;
        }
    }
}

// ---------------- fused: fp16 GEMM + tanh + score + exp-sum + attn partial ----
// 256 threads / 8 warps as 2 m-groups x 4 n-groups; 2 CTAs/SM.
// Tile M=64 tok x N=256 e x K=256. Warp (wm, wn): tokens [32wm,32wm+32),
// e-slice [64wn, 64wn+64). A tiles stay resident (4 stages) for the epilogue.
__global__ void __launch_bounds__(256, 2) score_kernel(
    const float* __restrict__ values,
    const float* __restrict__ Wscore) {

    extern __shared__ char sm[];
    const unsigned sb = smem_u32(sm);
    const int tid = threadIdx.x, wid = tid >> 5, lane = tid & 31;
    const int wm = wid >> 2, wn = wid & 3;
    const int b = blockIdx.y, t0 = blockIdx.x * 64;

    // pq / Wscore into smem
    {
        ((float*)(sm + SB_PQ))[tid] = g_projq[b * E_ + tid];
        ((float*)(sm + SB_W))[tid]  = Wscore[tid];
    }

    // loader index split
    const int tx = tid & 15, ry = tid >> 4;   // A: 16 float4-cols x 16 rows
    const int u  = tid & 7,  eb = tid >> 3;   // B: 8 16B-units x 32 e-rows
    const float4* vsrc = (const float4*)(values + ((size_t)b * T_ + t0) * D_);

    // per-lane ldmatrix geometry
    const unsigned arow  = lane & 15;
    const unsigned akoff = (lane >> 4) << 4;          // 0 or 16 bytes
    const unsigned brow  = (lane & 7) + ((lane & 16) >> 1);
    const unsigned bkoff = (lane & 8) << 1;           // 0 or 16 bytes

    float acc[2][8][4];
#pragma unroll
    for (int m = 0; m < 2; m++)
#pragma unroll
        for (int n = 0; n < 8; n++)
#pragma unroll
            for (int i = 0; i < 4; i++) acc[m][n][i] = 0.f;

    // ---- A chunk loader pieces (64 rows x 64 k-floats per chunk) ----
    float4 pv[4];
    auto lda = [&](int c) {
#pragma unroll
        for (int p = 0; p < 4; p++)
            pv[p] = vsrc[(size_t)(ry + 16 * p) * 64 + c * 16 + tx];
    };
    auto sta = [&](int c) {
        char* a = sm + SB_A(c);
#pragma unroll
        for (int p = 0; p < 4; p++) {
            const int row = ry + 16 * p;
            float4 v = pv[p];
            unsigned h01, h23;
            asm("cvt.rn.f16x2.f32 %0, %1, %2;" : "=r"(h01) : "f"(v.y), "f"(v.x));
            asm("cvt.rn.f16x2.f32 %0, %1, %2;" : "=r"(h23) : "f"(v.w), "f"(v.z));
            unsigned off = sw128((unsigned)(row * 128 + tx * 8));
            *(uint2*)(a + off) = make_uint2(h01, h23);
        }
    };
    auto ldb = [&](int c, int s) {
#pragma unroll
        for (int p = 0; p < 8; p++) {
            const int e = eb + 32 * p;
            const unsigned doff = sw128((unsigned)(e * 128 + u * 16));
            cpasync16(sb + SB_B(s) + doff, g_Wvf + (size_t)e * D_ + c * 64 + u * 8);
        }
        cp_commit();
    };

    // prologue: chunk 0 -> A stage 0, B stage 0
    lda(0);
    ldb(0, 0);
    sta(0);
    cp_wait0();
    __syncthreads();

    for (int c = 0; c < 4; c++) {
        const int s = c & 1;
        if (c < 3) {                 // prefetch next chunk
            lda(c + 1);
            ldb(c + 1, s ^ 1);
        }
        // ---- compute chunk c ----
        const unsigned ab = sb + SB_A(c), bb = sb + SB_B(s);
#pragma unroll
        for (int kk = 0; kk < 4; kk++) {
            unsigned A[2][4];
#pragma unroll
            for (int mb = 0; mb < 2; mb++) {
                const unsigned aoff =
                    sw128((wm * 32 + mb * 16 + arow) * 128 + (unsigned)kk * 32 + akoff);
                ldsm4(A[mb], ab + aoff);
            }
#pragma unroll
            for (int g = 0; g < 4; g++) {
                unsigned Bv[4];
                const unsigned boff =
                    sw128((wn * 64 + g * 16 + brow) * 128 + (unsigned)kk * 32 + bkoff);
                ldsm4(Bv, bb + boff);
#pragma unroll
                for (int mb = 0; mb < 2; mb++) {
                    mma16816(acc[mb][2 * g],     A[mb], Bv[0], Bv[1]);
                    mma16816(acc[mb][2 * g + 1], A[mb], Bv[2], Bv[3]);
                }
            }
        }
        if (c < 3) {
            sta(c + 1);
            cp_wait0();
        }
        __syncthreads();
    }

    // ---- epilogue 1: tanh + dot(Wscore) + score + exp-sum ----
    const float* pq = (const float*)(sm + SB_PQ);
    const float* w  = (const float*)(sm + SB_W);
    float* red = (float*)(sm + SB_RED);

    const int c0 = wn * 64 + (lane & 3) * 2;
#pragma unroll
    for (int mb = 0; mb < 2; mb++) {
        float r0 = 0.f, r1 = 0.f;
#pragma unroll
        for (int nb = 0; nb < 8; nb++) {
            const int ca = c0 + nb * 8, cb = ca + 1;
            const float pqa = pq[ca], pqb = pq[cb];
            const float wa = w[ca],  wb = w[cb];
            r0 += fast_tanh(acc[mb][nb][0] + pqa) * wa;
            r0 += fast_tanh(acc[mb][nb][1] + pqb) * wb;
            r1 += fast_tanh(acc[mb][nb][2] + pqa) * wa;
            r1 += fast_tanh(acc[mb][nb][3] + pqb) * wb;
        }
#pragma unroll
        for (int off = 1; off <= 2; off <<= 1) {
            r0 += __shfl_xor_sync(0xffffffffu, r0, off);
            r1 += __shfl_xor_sync(0xffffffffu, r1, off);
        }
        if ((lane & 3) == 0) {
            const int tok = wm * 32 + mb * 16 + (lane >> 2);
            red[tok * 5 + wn]       = r0;
            red[(tok + 8) * 5 + wn] = r1;
        }
    }
    __syncthreads();

    float* wbuf  = (float*)(sm + SB_WB);
    float* sattn = (float*)(sm + SB_SAT);
    if (tid < 64) {
        float s = red[tid * 5] + red[tid * 5 + 1] + red[tid * 5 + 2] + red[tid * 5 + 3];
        g_scores[b * T_ + t0 + tid] = s;
        // unnormalized softmax weight (no max shift: |score| <= ||Wscore||_1 ~ 13)
        float e = __expf(s);
        wbuf[tid] = e;
        float esum = e;
#pragma unroll
        for (int off = 16; off > 0; off >>= 1)
            esum += __shfl_xor_sync(0xffffffffu, esum, off);
        if (lane == 0) atomicAdd(&g_sum[b], esum);
    }
    sattn[tid] = 0.f;
    __syncthreads();

    // ---- epilogue 2: attn partial from resident fp16 A tiles ----
    {
        const int dgrp = tid & 63;         // 64 d-groups of 4
        const int sub  = tid >> 6;         // token subset 0..3
        const int cd   = dgrp >> 4;        // A stage (k-chunk)
        const unsigned col8 = (unsigned)(dgrp & 15) * 8;
        const char* abase = sm + SB_A(cd);
        float a0 = 0.f, a1 = 0.f, a2 = 0.f, a3 = 0.f;
#pragma unroll
        for (int i = 0; i < 16; i++) {
            const int t = sub + i * 4;
            const float wt = wbuf[t];
            uint2 hv = *(const uint2*)(abase + sw128((unsigned)(t * 128) + col8));
            float2 f0 = __half22float2(*reinterpret_cast<__half2*>(&hv.x));
            float2 f1 = __half22float2(*reinterpret_cast<__half2*>(&hv.y));
            a0 = fmaf(wt, f0.x, a0);
            a1 = fmaf(wt, f0.y, a1);
            a2 = fmaf(wt, f1.x, a2);
            a3 = fmaf(wt, f1.y, a3);
        }
        const int d0 = dgrp * 4;
        atomicAdd(&sattn[d0 + 0], a0);
        atomicAdd(&sattn[d0 + 1], a1);
        atomicAdd(&sattn[d0 + 2], a2);
        atomicAdd(&sattn[d0 + 3], a3);
    }
    __syncthreads();
    atomicAdd(&g_attn[b * D_ + tid], sattn[tid]);
}

// ---------------- final: alignments + attentions (normalize) ----------------
// One 1024-thread block per batch; thread handles 4 tokens via float4.
__global__ void align_kernel(float* __restrict__ out) {
    const int b = blockIdx.x, tid = threadIdx.x;   // 1024 threads
    const float inv = 1.f / g_sum[b];
    float4 s = ((const float4*)(g_scores + (size_t)b * T_))[tid];
    float4 r = make_float4(__expf(s.x) * inv, __expf(s.y) * inv,
                           __expf(s.z) * inv, __expf(s.w) * inv);
    ((float4*)(out + B_ * D_ + (size_t)b * T_))[tid] = r;
    if (tid < D_)
        out[b * D_ + tid] = g_attn[b * D_ + tid] * inv;
}

// ---------------- launch ----------------
extern "C" void kernel_launch(void* const* d_in, const int* in_sizes, int n_in,
                              void* d_out, int out_size) {
    const float* query  = (const float*)d_in[0];
    const float* values = (const float*)d_in[1];
    const float* Wv     = (const float*)d_in[2];
    const float* Wu     = (const float*)d_in[3];
    const float* Wscore = (const float*)d_in[4];
    float* out = (float*)d_out;

    cudaFuncSetAttribute(score_kernel,
                         cudaFuncAttributeMaxDynamicSharedMemorySize, SMEM_TOTAL);

    prep_kernel<<<40, 1024>>>(Wv, query, Wu);
    score_kernel<<<dim3(T_ / 64, B_), 256, SMEM_TOTAL>>>(values, Wscore);
    align_kernel<<<B_, 1024>>>(out);
}

// round 17
// speedup vs baseline: 1.7109x; 1.0526x over previous
#include <cuda_runtime.h>
#include <cuda_fp16.h>

#define B_   32
#define T_   4096
#define D_   256
#define DQ_  512
#define E_   256

// ---------------- scratch (static device globals) ----------------
__device__ float g_scores[B_ * T_];
__device__ float g_projq4[B_ * 4 * E_];           // per-k-quarter partials
__device__ float g_sum[B_];
__device__ float g_attn[B_ * D_];                 // unnormalized attention accum
__device__ __align__(16) __half g_Wvf[E_ * D_];   // [e][k] transposed fp16

// ---------------- helpers ----------------
__device__ __forceinline__ unsigned smem_u32(const void* p) {
    unsigned a;
    asm("{ .reg .u64 t; cvta.to.shared.u64 t, %1; cvt.u32.u64 %0, t; }"
        : "=r"(a) : "l"(p));
    return a;
}
__device__ __forceinline__ unsigned sw128(unsigned b) { return b ^ ((b >> 3) & 0x70); }

__device__ __forceinline__ void ldsm4(unsigned r[4], unsigned addr) {
    asm volatile("ldmatrix.sync.aligned.m8n8.x4.shared.b16 {%0,%1,%2,%3}, [%4];"
                 : "=r"(r[0]), "=r"(r[1]), "=r"(r[2]), "=r"(r[3]) : "r"(addr));
}
__device__ __forceinline__ void mma16816(float d[4], const unsigned a[4],
                                         unsigned b0, unsigned b1) {
    asm volatile(
        "mma.sync.aligned.m16n8k16.row.col.f32.f16.f16.f32 "
        "{%0,%1,%2,%3}, {%4,%5,%6,%7}, {%8,%9}, {%0,%1,%2,%3};"
        : "+f"(d[0]), "+f"(d[1]), "+f"(d[2]), "+f"(d[3])
        : "r"(a[0]), "r"(a[1]), "r"(a[2]), "r"(a[3]), "r"(b0), "r"(b1));
}
__device__ __forceinline__ void cpasync16(unsigned dst, const void* src) {
    asm volatile("cp.async.cg.shared.global [%0], [%1], 16;" :: "r"(dst), "l"(src));
}
__device__ __forceinline__ void cp_commit() { asm volatile("cp.async.commit_group;"); }
__device__ __forceinline__ void cp_wait0()  { asm volatile("cp.async.wait_group 0;" ::: "memory"); }

// single-MUFU tanh (MUFU.TANH, sm_75+)
__device__ __forceinline__ float fast_tanh(float x) {
    float y;
    asm("tanh.approx.f32 %0, %1;" : "=f"(y) : "f"(x));
    return y;
}

// smem layout (bytes):
//   A: 4 stages (one per K-chunk, kept live for the attn epilogue), 8KB each
//   B: 2 stages (double-buffered), 32KB each
#define SB_A(c)     ((c) * 8192)
#define SB_B(s)     (32768 + (s) * 32768)
#define SB_PQ       98304
#define SB_W        99328
#define SB_RED      100352                 // 64*5*4 = 1280
#define SB_WB       101632                 // 64 floats: exp(score)
#define SB_SAT      101888                 // 256 floats: CTA attn partial
#define SMEM_TOTAL  102912

// ---------------- prep: Wv->fp16T (blocks 0-7), proj_q partials (8-135) -----
// 1024 threads per block.
// projq: block = (b, k-quarter); 256 e x 4 sub-slices of 32 k each -> each
// thread issues 32 independent loads (ONE latency window), smem-reduce subs.
__global__ void prep_kernel(const float* __restrict__ Wv,
                            const float* __restrict__ query,
                            const float* __restrict__ Wu) {
    const int blk = blockIdx.x;
    const int tid = threadIdx.x;            // 1024
    if (blk < 8) {
        const int e  = tid & 255;
        const int k0 = (blk * 4 + (tid >> 8)) * 8;
        float v[8];
#pragma unroll
        for (int j = 0; j < 8; j++)
            v[j] = Wv[(size_t)(k0 + j) * E_ + e];
        unsigned p0, p1, p2, p3;
        asm("cvt.rn.f16x2.f32 %0, %1, %2;" : "=r"(p0) : "f"(v[1]), "f"(v[0]));
        asm("cvt.rn.f16x2.f32 %0, %1, %2;" : "=r"(p1) : "f"(v[3]), "f"(v[2]));
        asm("cvt.rn.f16x2.f32 %0, %1, %2;" : "=r"(p2) : "f"(v[5]), "f"(v[4]));
        asm("cvt.rn.f16x2.f32 %0, %1, %2;" : "=r"(p3) : "f"(v[7]), "f"(v[6]));
        *(uint4*)((char*)g_Wvf + ((size_t)e * D_ + k0) * 2) =
            make_uint4(p0, p1, p2, p3);
        // zero accumulators (8 blocks x 1024 threads cover B_*D_ = 8192)
        g_attn[blk * 1024 + tid] = 0.f;
        if (blk == 0 && tid < B_) g_sum[tid] = 0.f;
    } else {
        // proj_q partial for b = (blk-8)>>2, k-quarter kq = (blk-8)&3
        const int b  = (blk - 8) >> 2;
        const int kq = (blk - 8) & 3;
        const int e   = tid & 255;
        const int sub = tid >> 8;           // 0..3, k in [kq*128+sub*32, +32)
        __shared__ float q[128];
        __shared__ float part[4][E_];
        if (tid < 128) q[tid] = query[b * DQ_ + kq * 128 + tid];
        __syncthreads();
        float a0 = 0.f, a1 = 0.f, a2 = 0.f, a3 = 0.f;
        const float* qk = q + sub * 32;
        const float* wu = Wu + (size_t)(kq * 128 + sub * 32) * E_ + e;
#pragma unroll
        for (int k = 0; k < 32; k += 4) {
            a0 = fmaf(qk[k],     wu[(size_t)(k)     * E_], a0);
            a1 = fmaf(qk[k + 1], wu[(size_t)(k + 1) * E_], a1);
            a2 = fmaf(qk[k + 2], wu[(size_t)(k + 2) * E_], a2);
            a3 = fmaf(qk[k + 3], wu[(size_t)(k + 3) * E_], a3);
        }
        part[sub][e] = (a0 + a1) + (a2 + a3);
        __syncthreads();
        if (sub == 0)
            g_projq4[(b * 4 + kq) * E_ + e] =
                part[0][e] + part[1][e] + part[2][e] + part[3][e];
    }
}

// ---------------- fused: fp16 GEMM + tanh + score + exp-sum + attn partial ----
// 256 threads / 8 warps as 2 m-groups x 4 n-groups; 2 CTAs/SM.
// Tile M=64 tok x N=256 e x K=256. Warp (wm, wn): tokens [32wm,32wm+32),
// e-slice [64wn, 64wn+64). A tiles stay resident (4 stages) for the epilogue.
__global__ void __launch_bounds__(256, 2) score_kernel(
    const float* __restrict__ values,
    const float* __restrict__ Wscore) {

    extern __shared__ char sm[];
    const unsigned sb = smem_u32(sm);
    const int tid = threadIdx.x, wid = tid >> 5, lane = tid & 31;
    const int wm = wid >> 2, wn = wid & 3;
    const int b = blockIdx.y, t0 = blockIdx.x * 64;

    // pq (sum of 4 k-quarter partials) / Wscore into smem
    {
        const float* p4 = g_projq4 + b * 4 * E_;
        ((float*)(sm + SB_PQ))[tid] = (p4[tid] + p4[E_ + tid]) +
                                      (p4[2 * E_ + tid] + p4[3 * E_ + tid]);
        ((float*)(sm + SB_W))[tid]  = Wscore[tid];
    }

    // loader index split
    const int tx = tid & 15, ry = tid >> 4;   // A: 16 float4-cols x 16 rows
    const int u  = tid & 7,  eb = tid >> 3;   // B: 8 16B-units x 32 e-rows
    const float4* vsrc = (const float4*)(values + ((size_t)b * T_ + t0) * D_);

    // per-lane ldmatrix geometry
    const unsigned arow  = lane & 15;
    const unsigned akoff = (lane >> 4) << 4;          // 0 or 16 bytes
    const unsigned brow  = (lane & 7) + ((lane & 16) >> 1);
    const unsigned bkoff = (lane & 8) << 1;           // 0 or 16 bytes

    float acc[2][8][4];
#pragma unroll
    for (int m = 0; m < 2; m++)
#pragma unroll
        for (int n = 0; n < 8; n++)
#pragma unroll
            for (int i = 0; i < 4; i++) acc[m][n][i] = 0.f;

    // ---- A chunk loader pieces (64 rows x 64 k-floats per chunk) ----
    float4 pv[4];
    auto lda = [&](int c) {
#pragma unroll
        for (int p = 0; p < 4; p++)
            pv[p] = vsrc[(size_t)(ry + 16 * p) * 64 + c * 16 + tx];
    };
    auto sta = [&](int c) {
        char* a = sm + SB_A(c);
#pragma unroll
        for (int p = 0; p < 4; p++) {
            const int row = ry + 16 * p;
            float4 v = pv[p];
            unsigned h01, h23;
            asm("cvt.rn.f16x2.f32 %0, %1, %2;" : "=r"(h01) : "f"(v.y), "f"(v.x));
            asm("cvt.rn.f16x2.f32 %0, %1, %2;" : "=r"(h23) : "f"(v.w), "f"(v.z));
            unsigned off = sw128((unsigned)(row * 128 + tx * 8));
            *(uint2*)(a + off) = make_uint2(h01, h23);
        }
    };
    auto ldb = [&](int c, int s) {
#pragma unroll
        for (int p = 0; p < 8; p++) {
            const int e = eb + 32 * p;
            const unsigned doff = sw128((unsigned)(e * 128 + u * 16));
            cpasync16(sb + SB_B(s) + doff, g_Wvf + (size_t)e * D_ + c * 64 + u * 8);
        }
        cp_commit();
    };

    // prologue: chunk 0 -> A stage 0, B stage 0
    lda(0);
    ldb(0, 0);
    sta(0);
    cp_wait0();
    __syncthreads();

    for (int c = 0; c < 4; c++) {
        const int s = c & 1;
        if (c < 3) {                 // prefetch next chunk
            lda(c + 1);
            ldb(c + 1, s ^ 1);
        }
        // ---- compute chunk c ----
        const unsigned ab = sb + SB_A(c), bb = sb + SB_B(s);
#pragma unroll
        for (int kk = 0; kk < 4; kk++) {
            unsigned A[2][4];
#pragma unroll
            for (int mb = 0; mb < 2; mb++) {
                const unsigned aoff =
                    sw128((wm * 32 + mb * 16 + arow) * 128 + (unsigned)kk * 32 + akoff);
                ldsm4(A[mb], ab + aoff);
            }
#pragma unroll
            for (int g = 0; g < 4; g++) {
                unsigned Bv[4];
                const unsigned boff =
                    sw128((wn * 64 + g * 16 + brow) * 128 + (unsigned)kk * 32 + bkoff);
                ldsm4(Bv, bb + boff);
#pragma unroll
                for (int mb = 0; mb < 2; mb++) {
                    mma16816(acc[mb][2 * g],     A[mb], Bv[0], Bv[1]);
                    mma16816(acc[mb][2 * g + 1], A[mb], Bv[2], Bv[3]);
                }
            }
        }
        if (c < 3) {
            sta(c + 1);
            cp_wait0();
        }
        __syncthreads();
    }

    // ---- epilogue 1: tanh + dot(Wscore) + score + exp-sum ----
    const float* pq = (const float*)(sm + SB_PQ);
    const float* w  = (const float*)(sm + SB_W);
    float* red = (float*)(sm + SB_RED);

    const int c0 = wn * 64 + (lane & 3) * 2;
#pragma unroll
    for (int mb = 0; mb < 2; mb++) {
        float r0 = 0.f, r1 = 0.f;
#pragma unroll
        for (int nb = 0; nb < 8; nb++) {
            const int ca = c0 + nb * 8, cb = ca + 1;
            const float pqa = pq[ca], pqb = pq[cb];
            const float wa = w[ca],  wb = w[cb];
            r0 += fast_tanh(acc[mb][nb][0] + pqa) * wa;
            r0 += fast_tanh(acc[mb][nb][1] + pqb) * wb;
            r1 += fast_tanh(acc[mb][nb][2] + pqa) * wa;
            r1 += fast_tanh(acc[mb][nb][3] + pqb) * wb;
        }
#pragma unroll
        for (int off = 1; off <= 2; off <<= 1) {
            r0 += __shfl_xor_sync(0xffffffffu, r0, off);
            r1 += __shfl_xor_sync(0xffffffffu, r1, off);
        }
        if ((lane & 3) == 0) {
            const int tok = wm * 32 + mb * 16 + (lane >> 2);
            red[tok * 5 + wn]       = r0;
            red[(tok + 8) * 5 + wn] = r1;
        }
    }
    __syncthreads();

    float* wbuf  = (float*)(sm + SB_WB);
    float* sattn = (float*)(sm + SB_SAT);
    if (tid < 64) {
        float s = red[tid * 5] + red[tid * 5 + 1] + red[tid * 5 + 2] + red[tid * 5 + 3];
        g_scores[b * T_ + t0 + tid] = s;
        // unnormalized softmax weight (no max shift: |score| <= ||Wscore||_1 ~ 13)
        float e = __expf(s);
        wbuf[tid] = e;
        float esum = e;
#pragma unroll
        for (int off = 16; off > 0; off >>= 1)
            esum += __shfl_xor_sync(0xffffffffu, esum, off);
        if (lane == 0) atomicAdd(&g_sum[b], esum);
    }
    sattn[tid] = 0.f;
    __syncthreads();

    // ---- epilogue 2: attn partial from resident fp16 A tiles ----
    {
        const int dgrp = tid & 63;         // 64 d-groups of 4
        const int sub  = tid >> 6;         // token subset 0..3
        const int cd   = dgrp >> 4;        // A stage (k-chunk)
        const unsigned col8 = (unsigned)(dgrp & 15) * 8;
        const char* abase = sm + SB_A(cd);
        float a0 = 0.f, a1 = 0.f, a2 = 0.f, a3 = 0.f;
#pragma unroll
        for (int i = 0; i < 16; i++) {
            const int t = sub + i * 4;
            const float wt = wbuf[t];
            uint2 hv = *(const uint2*)(abase + sw128((unsigned)(t * 128) + col8));
            float2 f0 = __half22float2(*reinterpret_cast<__half2*>(&hv.x));
            float2 f1 = __half22float2(*reinterpret_cast<__half2*>(&hv.y));
            a0 = fmaf(wt, f0.x, a0);
            a1 = fmaf(wt, f0.y, a1);
            a2 = fmaf(wt, f1.x, a2);
            a3 = fmaf(wt, f1.y, a3);
        }
        const int d0 = dgrp * 4;
        atomicAdd(&sattn[d0 + 0], a0);
        atomicAdd(&sattn[d0 + 1], a1);
        atomicAdd(&sattn[d0 + 2], a2);
        atomicAdd(&sattn[d0 + 3], a3);
    }
    __syncthreads();
    atomicAdd(&g_attn[b * D_ + tid], sattn[tid]);
}

// ---------------- final: alignments + attentions (normalize) ----------------
// One 1024-thread block per batch; thread handles 4 tokens via float4.
__global__ void align_kernel(float* __restrict__ out) {
    const int b = blockIdx.x, tid = threadIdx.x;   // 1024 threads
    const float inv = 1.f / g_sum[b];
    float4 s = ((const float4*)(g_scores + (size_t)b * T_))[tid];
    float4 r = make_float4(__expf(s.x) * inv, __expf(s.y) * inv,
                           __expf(s.z) * inv, __expf(s.w) * inv);
    ((float4*)(out + B_ * D_ + (size_t)b * T_))[tid] = r;
    if (tid < D_)
        out[b * D_ + tid] = g_attn[b * D_ + tid] * inv;
}

// ---------------- launch ----------------
extern "C" void kernel_launch(void* const* d_in, const int* in_sizes, int n_in,
                              void* d_out, int out_size) {
    const float* query  = (const float*)d_in[0];
    const float* values = (const float*)d_in[1];
    const float* Wv     = (const float*)d_in[2];
    const float* Wu     = (const float*)d_in[3];
    const float* Wscore = (const float*)d_in[4];
    float* out = (float*)d_out;

    cudaFuncSetAttribute(score_kernel,
                         cudaFuncAttributeMaxDynamicSharedMemorySize, SMEM_TOTAL);

    prep_kernel<<<136, 1024>>>(Wv, query, Wu);
    score_kernel<<<dim3(T_ / 64, B_), 256, SMEM_TOTAL>>>(values, Wscore);
    align_kernel<<<B_, 1024>>>(out);
}